// round 12
// baseline (speedup 1.0000x reference)
#include <cuda_runtime.h>
#include <cuda_bf16.h>
#include <cstdint>
#include <cstddef>

// ---------------------------------------------------------------------------
//   x[N,256], batch[N] int32 sorted, W_g1[256,256], W_g2[256,8],
//   W_n1[256,256], b_n1[256], W_n2[256,256], b_n2[256] -> out[1024,256] fp32
//   Engine: mma.sync m16n8k16 bf16 hi/lo 3-pass. 256-thread CTAs, 2 CTAs/SM.
//   R9 mainloops (best). NEW: k_stats fused into k2's prologue (per-tile
//   graph stats recomputed under the cp.async shadow); out zeroed in k_prep.
// ---------------------------------------------------------------------------

#define N_MAX 200000
#define MAX_TILES ((N_MAX + 63) / 64)

__device__ float g_alpha[(size_t)N_MAX * 8];    // raw alpha (never rewritten)
// fragment-ordered weights, hi/lo interleaved:
// [w(3)][kstep(16)][nfrag(32)][lane(32)] uint4 = {hi.x, hi.y, lo.x, lo.y}
__device__ uint4 g_Wfrag4[3 * 16 * 32 * 32];
// H in A-fragment order: [tb16(row/16)][kb(16)][hl(2)][lane(32)] uint4
__device__ uint4 g_H[(size_t)MAX_TILES * 4 * 16 * 2 * 32];

// ---------------- helpers ---------------------------------------------------
__device__ __forceinline__ uint32_t smem_u32(const void* p) {
    uint32_t a;
    asm("{ .reg .u64 t; cvta.to.shared.u64 t, %1; cvt.u32.u64 %0, t; }"
        : "=r"(a) : "l"(p));
    return a;
}
__device__ __forceinline__ void split_bf16(float v, uint16_t& h, uint16_t& l) {
    __nv_bfloat16 hb = __float2bfloat16(v);
    h = __bfloat16_as_ushort(hb);
    l = __bfloat16_as_ushort(__float2bfloat16(v - __bfloat162float(hb)));
}
__device__ __forceinline__ void ldsm4(uint32_t* a, uint32_t addr) {
    asm volatile("ldmatrix.sync.aligned.m8n8.x4.shared.b16 {%0,%1,%2,%3}, [%4];"
                 : "=r"(a[0]), "=r"(a[1]), "=r"(a[2]), "=r"(a[3]) : "r"(addr));
}
__device__ __forceinline__ void lds128(uint32_t* a, uint32_t addr) {
    asm volatile("ld.shared.v4.u32 {%0,%1,%2,%3}, [%4];"
                 : "=r"(a[0]), "=r"(a[1]), "=r"(a[2]), "=r"(a[3]) : "r"(addr));
}
__device__ __forceinline__ void cpasync16z(uint32_t dst, const void* src, int sz) {
    asm volatile("cp.async.cg.shared.global [%0], [%1], 16, %2;\n"
                 :: "r"(dst), "l"(src), "r"(sz) : "memory");
}
__device__ __forceinline__ void mma16816(float* c, const uint32_t* a,
                                         uint32_t b0, uint32_t b1) {
    asm volatile(
        "mma.sync.aligned.m16n8k16.row.col.f32.bf16.bf16.f32 "
        "{%0,%1,%2,%3},{%4,%5,%6,%7},{%8,%9},{%0,%1,%2,%3};"
        : "+f"(c[0]), "+f"(c[1]), "+f"(c[2]), "+f"(c[3])
        : "r"(a[0]), "r"(a[1]), "r"(a[2]), "r"(a[3]), "r"(b0), "r"(b1));
}

// ---------------- smem layouts (bytes) --------------------------------------
#define P_A 528                    // bf16 tile pitch (32 rows x 256 cols + pad)
// k1 (per CTA, 32 rows):
#define OFF_AH1  0                 // 16896
#define OFF_AL1  16896             // 16896
#define OFF_WG2  33792             // 8192
#define OFF_ALP  41984             // 1024 (32x8 fp32)
#define OFF_B1K  43008             // 1024
#define SMEM_K1  44032

// k2 (per CTA, 64 rows): H staging [0..65536) overlays Wf [0..66048)
#define OFF_H    0
#define P_WF 1032
#define OFF_WF   0
#define OFF_B2K  66048             // 1024
#define OFF_BBK  67072             // 256 (64 ints)
#define OFF_BND  67328             // 64 (9 ints + pad)
#define OFF_RED  67392             // 1024 (32x8 fp32)
#define OFF_MS   68416             // 256 (8 graphs x 8 heads)
#define OFF_IS   68672             // 256
#define SMEM_K2  68928

// ---------------------------------------------------------------------------
// k_prep: pack 3 weights into fragment-ordered hi/lo-interleaved uint4;
// also zero the output buffer (atomic target for k2).
// ---------------------------------------------------------------------------
__global__ void k_prep(const float* __restrict__ Wn1,
                       const float* __restrict__ Wg1,
                       const float* __restrict__ Wn2,
                       float* __restrict__ out, int out_elems)
{
    const float* W = (blockIdx.y == 0) ? Wn1 : (blockIdx.y == 1) ? Wg1 : Wn2;
    const int i = blockIdx.x * 256 + threadIdx.x;
    const int lane = i & 31;
    const int nf   = (i >> 5) & 31;
    const int ks   = i >> 10;
    const int nn   = nf * 8 + (lane >> 2);
    const int k0   = ks * 16 + (lane & 3) * 2;

    float v[4];
    v[0] = W[(k0 + 0) * 256 + nn];
    v[1] = W[(k0 + 1) * 256 + nn];
    v[2] = W[(k0 + 8) * 256 + nn];
    v[3] = W[(k0 + 9) * 256 + nn];

    uint16_t h[4], l[4];
    #pragma unroll
    for (int q = 0; q < 4; ++q) split_bf16(v[q], h[q], l[q]);
    uint4 o;
    o.x = (uint32_t)h[0] | ((uint32_t)h[1] << 16);
    o.y = (uint32_t)h[2] | ((uint32_t)h[3] << 16);
    o.z = (uint32_t)l[0] | ((uint32_t)l[1] << 16);
    o.w = (uint32_t)l[2] | ((uint32_t)l[3] << 16);

    g_Wfrag4[(((blockIdx.y * 16 + ks) * 32 + nf) * 32) + lane] = o;

    // zero out[]
    const int gid = (blockIdx.y * gridDim.x + blockIdx.x) * 256 + threadIdx.x;
    const int tot = gridDim.x * gridDim.y * 256;
    for (int e = gid; e < out_elems; e += tot) out[e] = 0.f;
}

// ---------------------------------------------------------------------------
// k1: 32-row tile, 256 threads (8 warps). D[32,512] = x @ [Wn1 | Wg1].
// Warps nw 0..3 -> H fragments to g_H; nw 4..7 -> alpha = relu(D)@Wg2.
// (R9 mainloop, unchanged.)
// ---------------------------------------------------------------------------
__global__ __launch_bounds__(256, 2)
void k1(const float* __restrict__ x,
        const float* __restrict__ Wg2,
        const float* __restrict__ bn1,
        int n)
{
    extern __shared__ unsigned char sm[];
    const uint32_t sb = smem_u32(sm);
    float* Wg2s     = (float*)(sm + OFF_WG2);
    float* alpha_sm = (float*)(sm + OFF_ALP);
    float* b1s      = (float*)(sm + OFF_B1K);

    const int t = threadIdx.x;
    const int lane = t & 31, nw = t >> 5;
    const int g = lane >> 2, tig = lane & 3;
    const int m0 = blockIdx.x * 32;

    #pragma unroll
    for (int q = 0; q < 8; ++q) Wg2s[t + q * 256] = Wg2[t + q * 256];
    b1s[t] = bn1[t];
    alpha_sm[t] = 0.f;

    // stage x[m0:m0+32, 0:256] -> bf16 hi/lo smem
    #pragma unroll
    for (int e = 0; e < 8; ++e) {
        const int idx = t + e * 256;
        const int row = idx >> 6, q = idx & 63;
        const int m = m0 + row;
        float4 v = make_float4(0.f, 0.f, 0.f, 0.f);
        if (m < n) v = ((const float4*)(x + (size_t)m * 256))[q];
        uint16_t h0, h1, h2, h3, l0, l1, l2, l3;
        split_bf16(v.x, h0, l0);
        split_bf16(v.y, h1, l1);
        split_bf16(v.z, h2, l2);
        split_bf16(v.w, h3, l3);
        uint2 hp, lp;
        hp.x = (uint32_t)h0 | ((uint32_t)h1 << 16);
        hp.y = (uint32_t)h2 | ((uint32_t)h3 << 16);
        lp.x = (uint32_t)l0 | ((uint32_t)l1 << 16);
        lp.y = (uint32_t)l2 | ((uint32_t)l3 << 16);
        *(uint2*)(sm + OFF_AH1 + row * P_A + q * 8) = hp;
        *(uint2*)(sm + OFF_AL1 + row * P_A + q * 8) = lp;
    }
    __syncthreads();

    float acc[8][2][4];
    #pragma unroll
    for (int j = 0; j < 8; ++j)
        #pragma unroll
        for (int mf = 0; mf < 2; ++mf)
            #pragma unroll
            for (int q = 0; q < 4; ++q) acc[j][mf][q] = 0.f;

    const int img = (nw >= 4) ? 1 : 0;
    const int nb  = (nw & 3) * 8;

    #pragma unroll
    for (int ks = 0; ks < 16; ++ks) {
        const uint32_t abase = sb + (lane & 15) * P_A + ks * 32 + ((lane >> 4) << 4);
        uint32_t ah0[4], ah1[4], al0[4], al1[4];
        ldsm4(ah0, abase + OFF_AH1);
        ldsm4(ah1, abase + OFF_AH1 + 16 * P_A);
        ldsm4(al0, abase + OFF_AL1);
        ldsm4(al1, abase + OFF_AL1 + 16 * P_A);
        const int fb = ((img * 16 + ks) * 32 + nb) * 32 + lane;
        #pragma unroll
        for (int j = 0; j < 8; ++j) {
            const uint4 b = __ldg(&g_Wfrag4[fb + j * 32]);
            mma16816(acc[j][0], ah0, b.x, b.y);
            mma16816(acc[j][1], ah1, b.x, b.y);
            mma16816(acc[j][0], ah0, b.z, b.w);
            mma16816(acc[j][1], ah1, b.z, b.w);
            mma16816(acc[j][0], al0, b.x, b.y);
            mma16816(acc[j][1], al1, b.x, b.y);
        }
    }

    if (nw < 4) {
        // ---- H = relu(D + b1): A-fragment order (hi/lo) to g_H ----
        #pragma unroll
        for (int mf = 0; mf < 2; ++mf) {
            const size_t tb = (size_t)(blockIdx.x * 2 + mf);
            #pragma unroll
            for (int kp = 0; kp < 4; ++kp) {
                const int kb = nw * 4 + kp;
                uint4 Hh, Hl;
                #pragma unroll
                for (int je = 0; je < 2; ++je) {
                    const int j = kp * 2 + je;
                    const int c = nw * 64 + j * 8 + tig * 2;
                    const float v0 = fmaxf(acc[j][mf][0] + b1s[c],     0.f);
                    const float v1 = fmaxf(acc[j][mf][1] + b1s[c + 1], 0.f);
                    const float v2 = fmaxf(acc[j][mf][2] + b1s[c],     0.f);
                    const float v3 = fmaxf(acc[j][mf][3] + b1s[c + 1], 0.f);
                    uint16_t h0, h1, h2, h3, l0, l1, l2, l3;
                    split_bf16(v0, h0, l0);
                    split_bf16(v1, h1, l1);
                    split_bf16(v2, h2, l2);
                    split_bf16(v3, h3, l3);
                    const uint32_t hp0 = (uint32_t)h0 | ((uint32_t)h1 << 16);
                    const uint32_t hp1 = (uint32_t)h2 | ((uint32_t)h3 << 16);
                    const uint32_t lp0 = (uint32_t)l0 | ((uint32_t)l1 << 16);
                    const uint32_t lp1 = (uint32_t)l2 | ((uint32_t)l3 << 16);
                    if (je == 0) { Hh.x = hp0; Hh.y = hp1; Hl.x = lp0; Hl.y = lp1; }
                    else         { Hh.z = hp0; Hh.w = hp1; Hl.z = lp0; Hl.w = lp1; }
                }
                const size_t base = ((tb * 16 + kb) * 2) * 32 + lane;
                g_H[base]      = Hh;
                g_H[base + 32] = Hl;
            }
        }
    } else {
        // ---- alpha partial = relu(D) @ Wg2 over this warp's 64-col slice ----
        float pa[4][8];
        #pragma unroll
        for (int s = 0; s < 4; ++s)
            #pragma unroll
            for (int h = 0; h < 8; ++h) pa[s][h] = 0.f;

        #pragma unroll
        for (int mf = 0; mf < 2; ++mf)
            #pragma unroll
            for (int j = 0; j < 8; ++j) {
                const int c = (nw - 4) * 64 + j * 8 + tig * 2;
                const float d0 = fmaxf(acc[j][mf][0], 0.f);
                const float d1 = fmaxf(acc[j][mf][1], 0.f);
                const float d2 = fmaxf(acc[j][mf][2], 0.f);
                const float d3 = fmaxf(acc[j][mf][3], 0.f);
                const float4* wa = (const float4*)(Wg2s + c * 8);
                const float4* wb = (const float4*)(Wg2s + (c + 1) * 8);
                const float4 a0 = wa[0], a1 = wa[1], b0 = wb[0], b1 = wb[1];
                float* p0 = pa[mf * 2];
                float* p1 = pa[mf * 2 + 1];
                p0[0] = fmaf(d0, a0.x, fmaf(d1, b0.x, p0[0]));
                p0[1] = fmaf(d0, a0.y, fmaf(d1, b0.y, p0[1]));
                p0[2] = fmaf(d0, a0.z, fmaf(d1, b0.z, p0[2]));
                p0[3] = fmaf(d0, a0.w, fmaf(d1, b0.w, p0[3]));
                p0[4] = fmaf(d0, a1.x, fmaf(d1, b1.x, p0[4]));
                p0[5] = fmaf(d0, a1.y, fmaf(d1, b1.y, p0[5]));
                p0[6] = fmaf(d0, a1.z, fmaf(d1, b1.z, p0[6]));
                p0[7] = fmaf(d0, a1.w, fmaf(d1, b1.w, p0[7]));
                p1[0] = fmaf(d2, a0.x, fmaf(d3, b0.x, p1[0]));
                p1[1] = fmaf(d2, a0.y, fmaf(d3, b0.y, p1[1]));
                p1[2] = fmaf(d2, a0.z, fmaf(d3, b0.z, p1[2]));
                p1[3] = fmaf(d2, a0.w, fmaf(d3, b0.w, p1[3]));
                p1[4] = fmaf(d2, a1.x, fmaf(d3, b1.x, p1[4]));
                p1[5] = fmaf(d2, a1.y, fmaf(d3, b1.y, p1[5]));
                p1[6] = fmaf(d2, a1.z, fmaf(d3, b1.z, p1[6]));
                p1[7] = fmaf(d2, a1.w, fmaf(d3, b1.w, p1[7]));
            }
        #pragma unroll
        for (int off = 1; off <= 2; off <<= 1)
            #pragma unroll
            for (int s = 0; s < 4; ++s)
                #pragma unroll
                for (int h = 0; h < 8; ++h)
                    pa[s][h] += __shfl_xor_sync(0xffffffffu, pa[s][h], off);
        if (tig == 0) {
            #pragma unroll
            for (int s = 0; s < 4; ++s) {
                const int row = (s >> 1) * 16 + (s & 1) * 8 + g;
                #pragma unroll
                for (int h = 0; h < 8; ++h)
                    atomicAdd(&alpha_sm[row * 8 + h], pa[s][h]);
            }
        }
    }
    __syncthreads();

    const int row = t >> 3, h = t & 7;
    const int m = m0 + row;
    if (m < n) g_alpha[(size_t)m * 8 + h] = alpha_sm[row * 8 + h];
}

// ---------------------------------------------------------------------------
// k2: 64-row tile, 256 threads (8 warps). Warp tile 32x64 (mw2 = w&1,
// nw2 = w>>1). Prologue: cp.async H stage + INLINE per-graph softmax stats
// (binary-searched bounds, full-graph scans of g_alpha) under the copy shadow.
// Mainloop (R9): lds128 H + __ldg B. Epilogue: inline gates, segmented reduce.
// ---------------------------------------------------------------------------
__global__ __launch_bounds__(256, 2)
void k2(const int* __restrict__ batch,
        const float* __restrict__ bn2,
        float* __restrict__ out,
        int n)
{
    extern __shared__ unsigned char sm[];
    const uint32_t sb = smem_u32(sm);
    float* b2s = (float*)(sm + OFF_B2K);
    int*   bbs = (int*)(sm + OFF_BBK);
    int*   bnd = (int*)(sm + OFF_BND);
    float* red = (float*)(sm + OFF_RED);
    float* m_s = (float*)(sm + OFF_MS);
    float* i_s = (float*)(sm + OFF_IS);

    const int t = threadIdx.x;
    const int lane = t & 31, w = t >> 5;
    const int g = lane >> 2, tig = lane & 3;
    const int m0 = blockIdx.x * 64;
    const int mw2 = w & 1, nw2 = w >> 1;

    const int tbWritten = ((n + 31) / 32) * 2;

    // ---- issue H block staging (4096 uint4) via cp.async (zfill OOB) ----
    {
        const uint4* src = g_H + (size_t)blockIdx.x * 4096;
        #pragma unroll
        for (int e = 0; e < 16; ++e) {
            const int idx = t + e * 256;
            const int tbl = idx >> 10;
            const int sz = (blockIdx.x * 4 + tbl < tbWritten) ? 16 : 0;
            cpasync16z(sb + OFF_H + idx * 16, src + idx, sz);
        }
        asm volatile("cp.async.commit_group;\n" ::: "memory");
    }
    b2s[t] = bn2[t];
    if (t < 64) bbs[t] = (m0 + t < n) ? batch[m0 + t] : -1;
    __syncthreads();

    // ---- per-graph softmax stats (overlapped with cp.async) ----
    const int nv = (n - m0 < 64) ? (n - m0) : 64;
    const int gfirst = bbs[0];
    int ngr = bbs[nv - 1] - gfirst + 1;
    if (ngr > 8) ngr = 8;
    if (t <= ngr) {
        const int target = gfirst + t;
        int l = 0, r2 = n;
        while (l < r2) { int mid = (l + r2) >> 1; if (batch[mid] < target) l = mid + 1; else r2 = mid; }
        bnd[t] = l;
    }
    __syncthreads();

    const int slot = t >> 3, hh = t & 7;
    for (int gi = 0; gi < ngr; ++gi) {
        const int lo = bnd[gi], hi = bnd[gi + 1];
        float lm = -1e30f;
        for (int i = lo + slot; i < hi; i += 32)
            lm = fmaxf(lm, g_alpha[(size_t)i * 8 + hh]);
        red[slot * 8 + hh] = lm;
        __syncthreads();
        for (int s2 = 16; s2 > 0; s2 >>= 1) {
            if (slot < s2)
                red[slot * 8 + hh] = fmaxf(red[slot * 8 + hh], red[(slot + s2) * 8 + hh]);
            __syncthreads();
        }
        const float mv = red[hh];
        __syncthreads();
        float ls = 0.f;
        for (int i = lo + slot; i < hi; i += 32)
            ls += __expf(g_alpha[(size_t)i * 8 + hh] - mv);
        red[slot * 8 + hh] = ls;
        __syncthreads();
        for (int s2 = 16; s2 > 0; s2 >>= 1) {
            if (slot < s2)
                red[slot * 8 + hh] += red[(slot + s2) * 8 + hh];
            __syncthreads();
        }
        if (slot == 0) {
            m_s[gi * 8 + hh] = mv;
            i_s[gi * 8 + hh] = 1.f / (red[hh] + 1e-16f);
        }
        __syncthreads();
    }

    asm volatile("cp.async.wait_group 0;\n" ::: "memory");
    __syncthreads();

    float acc[2][8][4];
    #pragma unroll
    for (int mf = 0; mf < 2; ++mf)
        #pragma unroll
        for (int j = 0; j < 8; ++j)
            #pragma unroll
            for (int q = 0; q < 4; ++q) acc[mf][j][q] = 0.f;

    #pragma unroll
    for (int kb = 0; kb < 16; ++kb) {
        uint32_t ah0[4], al0[4], ah1[4], al1[4];
        const int tb0 = mw2 * 2;
        const uint32_t h0 = sb + OFF_H + ((((tb0 * 16 + kb) * 2) * 32) + lane) * 16;
        const uint32_t h1 = sb + OFF_H + (((((tb0 + 1) * 16 + kb) * 2) * 32) + lane) * 16;
        lds128(ah0, h0);
        lds128(al0, h0 + 512);
        lds128(ah1, h1);
        lds128(al1, h1 + 512);
        const int fb = ((2 * 16 + kb) * 32 + nw2 * 8) * 32 + lane;
        #pragma unroll
        for (int j = 0; j < 8; ++j) {
            const uint4 b = __ldg(&g_Wfrag4[fb + j * 32]);
            mma16816(acc[0][j], ah0, b.x, b.y);
            mma16816(acc[1][j], ah1, b.x, b.y);
            mma16816(acc[0][j], ah0, b.z, b.w);
            mma16816(acc[1][j], ah1, b.z, b.w);
            mma16816(acc[0][j], al0, b.x, b.y);
            mma16816(acc[1][j], al1, b.x, b.y);
        }
    }
    __syncthreads();   // all H reads done; Wf region overlays H

    // ---- weighted feats (inline gates) -> smem Wf[64][256] ----
    #pragma unroll
    for (int mf = 0; mf < 2; ++mf) {
        const int r0 = mw2 * 32 + mf * 16 + g;
        const int r1 = r0 + 8;
        float2 ga0 = make_float2(0.f, 0.f), ga1 = make_float2(0.f, 0.f);
        if (m0 + r0 < n) {
            const float2 a = *(const float2*)(g_alpha + (size_t)(m0 + r0) * 8 + tig * 2);
            int gl = bbs[r0] - gfirst; if (gl > 7) gl = 7;
            ga0.x = __expf(a.x - m_s[gl * 8 + tig * 2])     * i_s[gl * 8 + tig * 2];
            ga0.y = __expf(a.y - m_s[gl * 8 + tig * 2 + 1]) * i_s[gl * 8 + tig * 2 + 1];
        }
        if (m0 + r1 < n) {
            const float2 a = *(const float2*)(g_alpha + (size_t)(m0 + r1) * 8 + tig * 2);
            int gl = bbs[r1] - gfirst; if (gl > 7) gl = 7;
            ga1.x = __expf(a.x - m_s[gl * 8 + tig * 2])     * i_s[gl * 8 + tig * 2];
            ga1.y = __expf(a.y - m_s[gl * 8 + tig * 2 + 1]) * i_s[gl * 8 + tig * 2 + 1];
        }
        #pragma unroll
        for (int j = 0; j < 8; ++j) {
            const int c = nw2 * 64 + j * 8 + tig * 2;
            float2 s0, s1;
            s0.x = (acc[mf][j][0] + b2s[c])     * ga0.x;
            s0.y = (acc[mf][j][1] + b2s[c + 1]) * ga0.y;
            s1.x = (acc[mf][j][2] + b2s[c])     * ga1.x;
            s1.y = (acc[mf][j][3] + b2s[c + 1]) * ga1.y;
            *(float2*)(sm + OFF_WF + r0 * P_WF + c * 4) = s0;
            *(float2*)(sm + OFF_WF + r1 * P_WF + c * 4) = s1;
        }
    }
    __syncthreads();

    // ---- segmented reduction over 64 rows (sorted batch) -> atomicAdd out ----
    {
        const int c = t;
        float s = 0.f;
        int cur = -1;
        #pragma unroll 4
        for (int r = 0; r < 64; ++r) {
            if (m0 + r >= n) break;
            const int gid = bbs[r];
            if (gid != cur) {
                if (cur >= 0) atomicAdd(out + (size_t)cur * 256 + c, s);
                cur = gid;
                s = 0.f;
            }
            s += *(const float*)(sm + OFF_WF + r * P_WF + c * 4);
        }
        if (cur >= 0) atomicAdd(out + (size_t)cur * 256 + c, s);
    }
}

// ---------------------------------------------------------------------------
extern "C" void kernel_launch(void* const* d_in, const int* in_sizes, int n_in,
                              void* d_out, int out_size)
{
    const float* x     = (const float*)d_in[0];
    const int*   batch = (const int*)d_in[1];
    const float* Wg1   = (const float*)d_in[2];
    const float* Wg2   = (const float*)d_in[3];
    const float* Wn1   = (const float*)d_in[4];
    const float* bn1   = (const float*)d_in[5];
    const float* Wn2   = (const float*)d_in[6];
    const float* bn2   = (const float*)d_in[7];
    float* out = (float*)d_out;

    const int n = in_sizes[0] / 256;
    const int tiles32 = (n + 31) / 32;
    const int tiles64 = (n + 63) / 64;

    cudaFuncSetAttribute(k1, cudaFuncAttributeMaxDynamicSharedMemorySize, SMEM_K1);
    cudaFuncSetAttribute(k2, cudaFuncAttributeMaxDynamicSharedMemorySize, SMEM_K2);

    k_prep<<<dim3(64, 3), 256>>>(Wn1, Wg1, Wn2, out, out_size);
    k1<<<tiles32, 256, SMEM_K1>>>(x, Wg2, bn1, n);
    k2<<<tiles64, 256, SMEM_K2>>>(batch, bn2, out, n);
}

// round 13
// speedup vs baseline: 1.4913x; 1.4913x over previous
#include <cuda_runtime.h>
#include <cuda_fp16.h>
#include <cstdint>
#include <cstddef>

// ---------------------------------------------------------------------------
//   x[N,256], batch[N] int32 sorted, W_g1[256,256], W_g2[256,8],
//   W_n1[256,256], b_n1[256], W_n2[256,256], b_n2[256] -> out[1024,256] fp32
//   Engine: mma.sync m16n8k16 FP16, activation hi/lo 2-pass (x@wh exact in
//   fp16 pair; dropped term x*wl ~ 2^-11). 256-thread CTAs, 2 CTAs/SM.
//   Structure = R9 (best): k1 (32-row tiles, x@[Wn1|Wg1], alpha + H frags),
//   k_stats (gates in place + zero out), k2 (64-row tiles, cp.async H stage).
// ---------------------------------------------------------------------------

#define N_MAX 200000
#define MAX_TILES ((N_MAX + 63) / 64)

__device__ float g_alpha[(size_t)N_MAX * 8];    // alpha, then gates (in-place)
// fragment-ordered fp16 weights, 2 n-fragments packed per uint4:
// [w(3)][kstep(16)][nf2(16)][lane(32)] uint4 = {bj0.r0, bj0.r1, bj1.r0, bj1.r1}
__device__ uint4 g_Wfrag4[3 * 16 * 16 * 32];
// H (fp16 hi/lo) in A-fragment order: [tb16][kb(16)][hl(2)][lane(32)] uint4
__device__ uint4 g_H[(size_t)MAX_TILES * 4 * 16 * 2 * 32];

// ---------------- helpers ---------------------------------------------------
__device__ __forceinline__ uint32_t smem_u32(const void* p) {
    uint32_t a;
    asm("{ .reg .u64 t; cvta.to.shared.u64 t, %1; cvt.u32.u64 %0, t; }"
        : "=r"(a) : "l"(p));
    return a;
}
__device__ __forceinline__ void split_f16(float v, uint16_t& h, uint16_t& l) {
    __half hb = __float2half_rn(v);
    h = __half_as_ushort(hb);
    l = __half_as_ushort(__float2half_rn(v - __half2float(hb)));
}
__device__ __forceinline__ uint16_t f16(float v) {
    return __half_as_ushort(__float2half_rn(v));
}
__device__ __forceinline__ void ldsm4(uint32_t* a, uint32_t addr) {
    asm volatile("ldmatrix.sync.aligned.m8n8.x4.shared.b16 {%0,%1,%2,%3}, [%4];"
                 : "=r"(a[0]), "=r"(a[1]), "=r"(a[2]), "=r"(a[3]) : "r"(addr));
}
__device__ __forceinline__ void lds128(uint32_t* a, uint32_t addr) {
    asm volatile("ld.shared.v4.u32 {%0,%1,%2,%3}, [%4];"
                 : "=r"(a[0]), "=r"(a[1]), "=r"(a[2]), "=r"(a[3]) : "r"(addr));
}
__device__ __forceinline__ void cpasync16z(uint32_t dst, const void* src, int sz) {
    asm volatile("cp.async.cg.shared.global [%0], [%1], 16, %2;\n"
                 :: "r"(dst), "l"(src), "r"(sz) : "memory");
}
__device__ __forceinline__ void mma16816(float* c, const uint32_t* a,
                                         uint32_t b0, uint32_t b1) {
    asm volatile(
        "mma.sync.aligned.m16n8k16.row.col.f32.f16.f16.f32 "
        "{%0,%1,%2,%3},{%4,%5,%6,%7},{%8,%9},{%0,%1,%2,%3};"
        : "+f"(c[0]), "+f"(c[1]), "+f"(c[2]), "+f"(c[3])
        : "r"(a[0]), "r"(a[1]), "r"(a[2]), "r"(a[3]), "r"(b0), "r"(b1));
}

// ---------------- smem layouts (bytes) --------------------------------------
#define P_A 528                    // fp16 tile pitch (32 rows x 256 cols + pad)
// k1 (per CTA, 32 rows):
#define OFF_AH1  0                 // 16896
#define OFF_AL1  16896             // 16896
#define OFF_WG2  33792             // 8192
#define OFF_ALP  41984             // 1024 (32x8 fp32)
#define OFF_B1K  43008             // 1024
#define SMEM_K1  44032

// k2 (per CTA, 64 rows): H staging [0..65536) overlays Wf [0..66048)
#define OFF_H    0
#define P_WF 1032
#define OFF_WF   0
#define OFF_B2K  66048             // 1024
#define OFF_BBK  67072             // 256 (64 ints)
#define SMEM_K2  67328

// ---------------------------------------------------------------------------
// k_prep: pack 3 weights into fragment-pair-ordered fp16 uint4.
// For nf2 pair (nf=2*nf2, 2*nf2+1): n = nf*8 + (lane>>2), k0 = ks*16+(lane&3)*2;
// reg0 = {W[k0][n], W[k0+1][n]}, reg1 = {W[k0+8][n], W[k0+9][n]}.
// ---------------------------------------------------------------------------
__global__ void k_prep(const float* __restrict__ Wn1,
                       const float* __restrict__ Wg1,
                       const float* __restrict__ Wn2)
{
    const float* W = (blockIdx.y == 0) ? Wn1 : (blockIdx.y == 1) ? Wg1 : Wn2;
    const int i = blockIdx.x * 256 + threadIdx.x;   // 0..8191
    const int lane = i & 31;
    const int nf2  = (i >> 5) & 15;
    const int ks   = i >> 9;
    const int k0   = ks * 16 + (lane & 3) * 2;

    uint4 o;
    {
        const int nn = (2 * nf2) * 8 + (lane >> 2);
        o.x = (uint32_t)f16(W[(k0 + 0) * 256 + nn]) |
              ((uint32_t)f16(W[(k0 + 1) * 256 + nn]) << 16);
        o.y = (uint32_t)f16(W[(k0 + 8) * 256 + nn]) |
              ((uint32_t)f16(W[(k0 + 9) * 256 + nn]) << 16);
    }
    {
        const int nn = (2 * nf2 + 1) * 8 + (lane >> 2);
        o.z = (uint32_t)f16(W[(k0 + 0) * 256 + nn]) |
              ((uint32_t)f16(W[(k0 + 1) * 256 + nn]) << 16);
        o.w = (uint32_t)f16(W[(k0 + 8) * 256 + nn]) |
              ((uint32_t)f16(W[(k0 + 9) * 256 + nn]) << 16);
    }
    g_Wfrag4[(((blockIdx.y * 16 + ks) * 16 + nf2) * 32) + lane] = o;
}

// ---------------------------------------------------------------------------
// k1: 32-row tile, 256 threads (8 warps). D[32,512] = x @ [Wn1 | Wg1]
// (fp16 2-pass: (xh+xl)@wh). Warps nw 0..3 -> H fragments; nw 4..7 -> alpha.
// ---------------------------------------------------------------------------
__global__ __launch_bounds__(256, 2)
void k1(const float* __restrict__ x,
        const float* __restrict__ Wg2,
        const float* __restrict__ bn1,
        int n)
{
    extern __shared__ unsigned char sm[];
    const uint32_t sb = smem_u32(sm);
    float* Wg2s     = (float*)(sm + OFF_WG2);
    float* alpha_sm = (float*)(sm + OFF_ALP);
    float* b1s      = (float*)(sm + OFF_B1K);

    const int t = threadIdx.x;
    const int lane = t & 31, nw = t >> 5;
    const int g = lane >> 2, tig = lane & 3;
    const int m0 = blockIdx.x * 32;

    #pragma unroll
    for (int q = 0; q < 8; ++q) Wg2s[t + q * 256] = Wg2[t + q * 256];
    b1s[t] = bn1[t];
    alpha_sm[t] = 0.f;

    // stage x[m0:m0+32, 0:256] -> fp16 hi/lo smem
    #pragma unroll
    for (int e = 0; e < 8; ++e) {
        const int idx = t + e * 256;            // 0..2047 float4s
        const int row = idx >> 6, q = idx & 63;
        const int m = m0 + row;
        float4 v = make_float4(0.f, 0.f, 0.f, 0.f);
        if (m < n) v = ((const float4*)(x + (size_t)m * 256))[q];
        uint16_t h0, h1, h2, h3, l0, l1, l2, l3;
        split_f16(v.x, h0, l0);
        split_f16(v.y, h1, l1);
        split_f16(v.z, h2, l2);
        split_f16(v.w, h3, l3);
        uint2 hp, lp;
        hp.x = (uint32_t)h0 | ((uint32_t)h1 << 16);
        hp.y = (uint32_t)h2 | ((uint32_t)h3 << 16);
        lp.x = (uint32_t)l0 | ((uint32_t)l1 << 16);
        lp.y = (uint32_t)l2 | ((uint32_t)l3 << 16);
        *(uint2*)(sm + OFF_AH1 + row * P_A + q * 8) = hp;
        *(uint2*)(sm + OFF_AL1 + row * P_A + q * 8) = lp;
    }
    __syncthreads();

    float acc[8][2][4];
    #pragma unroll
    for (int j = 0; j < 8; ++j)
        #pragma unroll
        for (int mf = 0; mf < 2; ++mf)
            #pragma unroll
            for (int q = 0; q < 4; ++q) acc[j][mf][q] = 0.f;

    const int img = (nw >= 4) ? 1 : 0;
    const int nb2 = (nw & 3) * 4;   // nf2 base for this warp's 8 fragments

    #pragma unroll
    for (int ks = 0; ks < 16; ++ks) {
        const uint32_t abase = sb + (lane & 15) * P_A + ks * 32 + ((lane >> 4) << 4);
        uint32_t ah0[4], ah1[4], al0[4], al1[4];
        ldsm4(ah0, abase + OFF_AH1);
        ldsm4(ah1, abase + OFF_AH1 + 16 * P_A);
        ldsm4(al0, abase + OFF_AL1);
        ldsm4(al1, abase + OFF_AL1 + 16 * P_A);
        const int fb = ((img * 16 + ks) * 16 + nb2) * 32 + lane;
        #pragma unroll
        for (int q = 0; q < 4; ++q) {
            const uint4 b = __ldg(&g_Wfrag4[fb + q * 32]);
            const int j0 = 2 * q, j1 = 2 * q + 1;
            mma16816(acc[j0][0], ah0, b.x, b.y);
            mma16816(acc[j0][1], ah1, b.x, b.y);
            mma16816(acc[j0][0], al0, b.x, b.y);
            mma16816(acc[j0][1], al1, b.x, b.y);
            mma16816(acc[j1][0], ah0, b.z, b.w);
            mma16816(acc[j1][1], ah1, b.z, b.w);
            mma16816(acc[j1][0], al0, b.z, b.w);
            mma16816(acc[j1][1], al1, b.z, b.w);
        }
    }

    if (nw < 4) {
        // ---- H = relu(D + b1): fp16 hi/lo, A-fragment order to g_H ----
        #pragma unroll
        for (int mf = 0; mf < 2; ++mf) {
            const size_t tb = (size_t)(blockIdx.x * 2 + mf);
            #pragma unroll
            for (int kp = 0; kp < 4; ++kp) {
                const int kb = nw * 4 + kp;
                uint4 Hh, Hl;
                #pragma unroll
                for (int je = 0; je < 2; ++je) {
                    const int j = kp * 2 + je;
                    const int c = nw * 64 + j * 8 + tig * 2;
                    const float v0 = fmaxf(acc[j][mf][0] + b1s[c],     0.f);
                    const float v1 = fmaxf(acc[j][mf][1] + b1s[c + 1], 0.f);
                    const float v2 = fmaxf(acc[j][mf][2] + b1s[c],     0.f);
                    const float v3 = fmaxf(acc[j][mf][3] + b1s[c + 1], 0.f);
                    uint16_t h0, h1, h2, h3, l0, l1, l2, l3;
                    split_f16(v0, h0, l0);
                    split_f16(v1, h1, l1);
                    split_f16(v2, h2, l2);
                    split_f16(v3, h3, l3);
                    const uint32_t hp0 = (uint32_t)h0 | ((uint32_t)h1 << 16);
                    const uint32_t hp1 = (uint32_t)h2 | ((uint32_t)h3 << 16);
                    const uint32_t lp0 = (uint32_t)l0 | ((uint32_t)l1 << 16);
                    const uint32_t lp1 = (uint32_t)l2 | ((uint32_t)l3 << 16);
                    if (je == 0) { Hh.x = hp0; Hh.y = hp1; Hl.x = lp0; Hl.y = lp1; }
                    else         { Hh.z = hp0; Hh.w = hp1; Hl.z = lp0; Hl.w = lp1; }
                }
                const size_t base = ((tb * 16 + kb) * 2) * 32 + lane;
                g_H[base]      = Hh;
                g_H[base + 32] = Hl;
            }
        }
    } else {
        // ---- alpha partial = relu(D) @ Wg2 over this warp's 64-col slice ----
        float pa[4][8];
        #pragma unroll
        for (int s = 0; s < 4; ++s)
            #pragma unroll
            for (int h = 0; h < 8; ++h) pa[s][h] = 0.f;

        #pragma unroll
        for (int mf = 0; mf < 2; ++mf)
            #pragma unroll
            for (int j = 0; j < 8; ++j) {
                const int c = (nw - 4) * 64 + j * 8 + tig * 2;
                const float d0 = fmaxf(acc[j][mf][0], 0.f);
                const float d1 = fmaxf(acc[j][mf][1], 0.f);
                const float d2 = fmaxf(acc[j][mf][2], 0.f);
                const float d3 = fmaxf(acc[j][mf][3], 0.f);
                const float4* wa = (const float4*)(Wg2s + c * 8);
                const float4* wb = (const float4*)(Wg2s + (c + 1) * 8);
                const float4 a0 = wa[0], a1 = wa[1], b0 = wb[0], b1 = wb[1];
                float* p0 = pa[mf * 2];
                float* p1 = pa[mf * 2 + 1];
                p0[0] = fmaf(d0, a0.x, fmaf(d1, b0.x, p0[0]));
                p0[1] = fmaf(d0, a0.y, fmaf(d1, b0.y, p0[1]));
                p0[2] = fmaf(d0, a0.z, fmaf(d1, b0.z, p0[2]));
                p0[3] = fmaf(d0, a0.w, fmaf(d1, b0.w, p0[3]));
                p0[4] = fmaf(d0, a1.x, fmaf(d1, b1.x, p0[4]));
                p0[5] = fmaf(d0, a1.y, fmaf(d1, b1.y, p0[5]));
                p0[6] = fmaf(d0, a1.z, fmaf(d1, b1.z, p0[6]));
                p0[7] = fmaf(d0, a1.w, fmaf(d1, b1.w, p0[7]));
                p1[0] = fmaf(d2, a0.x, fmaf(d3, b0.x, p1[0]));
                p1[1] = fmaf(d2, a0.y, fmaf(d3, b0.y, p1[1]));
                p1[2] = fmaf(d2, a0.z, fmaf(d3, b0.z, p1[2]));
                p1[3] = fmaf(d2, a0.w, fmaf(d3, b0.w, p1[3]));
                p1[4] = fmaf(d2, a1.x, fmaf(d3, b1.x, p1[4]));
                p1[5] = fmaf(d2, a1.y, fmaf(d3, b1.y, p1[5]));
                p1[6] = fmaf(d2, a1.z, fmaf(d3, b1.z, p1[6]));
                p1[7] = fmaf(d2, a1.w, fmaf(d3, b1.w, p1[7]));
            }
        #pragma unroll
        for (int off = 1; off <= 2; off <<= 1)
            #pragma unroll
            for (int s = 0; s < 4; ++s)
                #pragma unroll
                for (int h = 0; h < 8; ++h)
                    pa[s][h] += __shfl_xor_sync(0xffffffffu, pa[s][h], off);
        if (tig == 0) {
            #pragma unroll
            for (int s = 0; s < 4; ++s) {
                const int row = (s >> 1) * 16 + (s & 1) * 8 + g;
                #pragma unroll
                for (int h = 0; h < 8; ++h)
                    atomicAdd(&alpha_sm[row * 8 + h], pa[s][h]);
            }
        }
    }
    __syncthreads();

    const int row = t >> 3, h = t & 7;
    const int m = m0 + row;
    if (m < n) g_alpha[(size_t)m * 8 + h] = alpha_sm[row * 8 + h];
}

// ---------------------------------------------------------------------------
// k_stats: per graph softmax stats; overwrite g_alpha with gates; zero out.
// ---------------------------------------------------------------------------
__global__ __launch_bounds__(256)
void k_stats(const int* __restrict__ batch,
             float* __restrict__ out,
             int n)
{
    const int b = blockIdx.x;
    const int t = threadIdx.x;

    int lo, hi;
    {
        int l = 0, r2 = n;
        while (l < r2) { int mid = (l + r2) >> 1; if (batch[mid] < b) l = mid + 1; else r2 = mid; }
        lo = l;
        r2 = n;
        while (l < r2) { int mid = (l + r2) >> 1; if (batch[mid] < b + 1) l = mid + 1; else r2 = mid; }
        hi = l;
    }

    __shared__ float red[256][8];
    __shared__ float mh[8];
    __shared__ float ih[8];

    float lm[8];
    #pragma unroll
    for (int q = 0; q < 8; ++q) lm[q] = -1e30f;
    for (int i = lo + t; i < hi; i += 256) {
        #pragma unroll
        for (int q = 0; q < 8; ++q)
            lm[q] = fmaxf(lm[q], g_alpha[(size_t)i * 8 + q]);
    }
    #pragma unroll
    for (int q = 0; q < 8; ++q) red[t][q] = lm[q];
    __syncthreads();
    for (int s2 = 128; s2 > 0; s2 >>= 1) {
        if (t < s2) {
            #pragma unroll
            for (int q = 0; q < 8; ++q)
                red[t][q] = fmaxf(red[t][q], red[t + s2][q]);
        }
        __syncthreads();
    }
    if (t < 8) mh[t] = red[0][t];
    __syncthreads();

    float m8[8];
    #pragma unroll
    for (int q = 0; q < 8; ++q) m8[q] = mh[q];

    float ls[8];
    #pragma unroll
    for (int q = 0; q < 8; ++q) ls[q] = 0.f;
    for (int i = lo + t; i < hi; i += 256) {
        #pragma unroll
        for (int q = 0; q < 8; ++q)
            ls[q] += __expf(g_alpha[(size_t)i * 8 + q] - m8[q]);
    }
    __syncthreads();
    #pragma unroll
    for (int q = 0; q < 8; ++q) red[t][q] = ls[q];
    __syncthreads();
    for (int s2 = 128; s2 > 0; s2 >>= 1) {
        if (t < s2) {
            #pragma unroll
            for (int q = 0; q < 8; ++q)
                red[t][q] += red[t + s2][q];
        }
        __syncthreads();
    }
    if (t < 8) ih[t] = 1.f / (red[0][t] + 1e-16f);
    __syncthreads();

    float i8[8];
    #pragma unroll
    for (int q = 0; q < 8; ++q) i8[q] = ih[q];

    for (long long e = (long long)lo * 8 + t; e < (long long)hi * 8; e += 256) {
        const int h = (int)(e & 7);
        g_alpha[e] = __expf(g_alpha[e] - m8[h]) * i8[h];
    }
    out[(size_t)b * 256 + t] = 0.f;
}

// ---------------------------------------------------------------------------
// k2: 64-row tile, 256 threads (8 warps). Warp tile 32x64 (mw2 = w&1,
// nw2 = w>>1). cp.async H stage; D2 = H @ Wn2 (fp16 2-pass) (+b2),
// gate-weight, segmented reduce, atomics. (R9 structure.)
// ---------------------------------------------------------------------------
__global__ __launch_bounds__(256, 2)
void k2(const int* __restrict__ batch,
        const float* __restrict__ bn2,
        float* __restrict__ out,
        int n)
{
    extern __shared__ unsigned char sm[];
    const uint32_t sb = smem_u32(sm);
    float* b2s = (float*)(sm + OFF_B2K);
    int*   bbs = (int*)(sm + OFF_BBK);

    const int t = threadIdx.x;
    const int lane = t & 31, w = t >> 5;
    const int g = lane >> 2, tig = lane & 3;
    const int m0 = blockIdx.x * 64;
    const int mw2 = w & 1, nw2 = w >> 1;

    const int tbWritten = ((n + 31) / 32) * 2;

    // ---- bulk-stage this tile's H block (4096 uint4) via cp.async (zfill) ----
    {
        const uint4* src = g_H + (size_t)blockIdx.x * 4096;
        #pragma unroll
        for (int e = 0; e < 16; ++e) {
            const int idx = t + e * 256;
            const int tbl = idx >> 10;
            const int sz = (blockIdx.x * 4 + tbl < tbWritten) ? 16 : 0;
            cpasync16z(sb + OFF_H + idx * 16, src + idx, sz);
        }
        asm volatile("cp.async.commit_group;\n" ::: "memory");
    }
    b2s[t] = bn2[t];
    if (t < 64) bbs[t] = (m0 + t < n) ? batch[m0 + t] : -1;
    asm volatile("cp.async.wait_group 0;\n" ::: "memory");
    __syncthreads();

    float acc[2][8][4];
    #pragma unroll
    for (int mf = 0; mf < 2; ++mf)
        #pragma unroll
        for (int j = 0; j < 8; ++j)
            #pragma unroll
            for (int q = 0; q < 4; ++q) acc[mf][j][q] = 0.f;

    #pragma unroll
    for (int kb = 0; kb < 16; ++kb) {
        uint32_t ah0[4], al0[4], ah1[4], al1[4];
        const int tb0 = mw2 * 2;
        const uint32_t h0 = sb + OFF_H + ((((tb0 * 16 + kb) * 2) * 32) + lane) * 16;
        const uint32_t h1 = sb + OFF_H + (((((tb0 + 1) * 16 + kb) * 2) * 32) + lane) * 16;
        lds128(ah0, h0);
        lds128(al0, h0 + 512);
        lds128(ah1, h1);
        lds128(al1, h1 + 512);
        const int fb = ((2 * 16 + kb) * 16 + nw2 * 4) * 32 + lane;
        #pragma unroll
        for (int q = 0; q < 4; ++q) {
            const uint4 b = __ldg(&g_Wfrag4[fb + q * 32]);
            const int j0 = 2 * q, j1 = 2 * q + 1;
            mma16816(acc[0][j0], ah0, b.x, b.y);
            mma16816(acc[1][j0], ah1, b.x, b.y);
            mma16816(acc[0][j0], al0, b.x, b.y);
            mma16816(acc[1][j0], al1, b.x, b.y);
            mma16816(acc[0][j1], ah0, b.z, b.w);
            mma16816(acc[1][j1], ah1, b.z, b.w);
            mma16816(acc[0][j1], al0, b.z, b.w);
            mma16816(acc[1][j1], al1, b.z, b.w);
        }
    }
    __syncthreads();   // all H reads done; Wf region overlays H

    // ---- weighted feats -> smem Wf[64][256] ----
    #pragma unroll
    for (int mf = 0; mf < 2; ++mf) {
        const int r0 = mw2 * 32 + mf * 16 + g;
        const int r1 = r0 + 8;
        float2 g0 = make_float2(0.f, 0.f), g1 = make_float2(0.f, 0.f);
        if (m0 + r0 < n) g0 = *(const float2*)(g_alpha + (size_t)(m0 + r0) * 8 + tig * 2);
        if (m0 + r1 < n) g1 = *(const float2*)(g_alpha + (size_t)(m0 + r1) * 8 + tig * 2);
        #pragma unroll
        for (int j = 0; j < 8; ++j) {
            const int c = nw2 * 64 + j * 8 + tig * 2;
            float2 s0, s1;
            s0.x = (acc[mf][j][0] + b2s[c])     * g0.x;
            s0.y = (acc[mf][j][1] + b2s[c + 1]) * g0.y;
            s1.x = (acc[mf][j][2] + b2s[c])     * g1.x;
            s1.y = (acc[mf][j][3] + b2s[c + 1]) * g1.y;
            *(float2*)(sm + OFF_WF + r0 * P_WF + c * 4) = s0;
            *(float2*)(sm + OFF_WF + r1 * P_WF + c * 4) = s1;
        }
    }
    __syncthreads();

    // ---- segmented reduction over 64 rows (sorted batch) -> atomicAdd out ----
    {
        const int c = t;
        float s = 0.f;
        int cur = -1;
        #pragma unroll 4
        for (int r = 0; r < 64; ++r) {
            if (m0 + r >= n) break;
            const int gid = bbs[r];
            if (gid != cur) {
                if (cur >= 0) atomicAdd(out + (size_t)cur * 256 + c, s);
                cur = gid;
                s = 0.f;
            }
            s += *(const float*)(sm + OFF_WF + r * P_WF + c * 4);
        }
        if (cur >= 0) atomicAdd(out + (size_t)cur * 256 + c, s);
    }
}

// ---------------------------------------------------------------------------
extern "C" void kernel_launch(void* const* d_in, const int* in_sizes, int n_in,
                              void* d_out, int out_size)
{
    const float* x     = (const float*)d_in[0];
    const int*   batch = (const int*)d_in[1];
    const float* Wg1   = (const float*)d_in[2];
    const float* Wg2   = (const float*)d_in[3];
    const float* Wn1   = (const float*)d_in[4];
    const float* bn1   = (const float*)d_in[5];
    const float* Wn2   = (const float*)d_in[6];
    const float* bn2   = (const float*)d_in[7];
    float* out = (float*)d_out;

    const int n = in_sizes[0] / 256;
    const int B = out_size / 256;
    const int tiles32 = (n + 31) / 32;
    const int tiles64 = (n + 63) / 64;

    cudaFuncSetAttribute(k1, cudaFuncAttributeMaxDynamicSharedMemorySize, SMEM_K1);
    cudaFuncSetAttribute(k2, cudaFuncAttributeMaxDynamicSharedMemorySize, SMEM_K2);

    k_prep<<<dim3(32, 3), 256>>>(Wn1, Wg1, Wn2);
    k1<<<tiles32, 256, SMEM_K1>>>(x, Wg2, bn1, n);
    k_stats<<<B, 256>>>(batch, out, n);
    k2<<<tiles64, 256, SMEM_K2>>>(batch, bn2, out, n);
}

// round 14
// speedup vs baseline: 1.7031x; 1.1420x over previous
#include <cuda_runtime.h>
#include <cuda_fp16.h>
#include <cstdint>
#include <cstddef>

// ---------------------------------------------------------------------------
//   x[N,256], batch[N] int32 sorted, W_g1[256,256], W_g2[256,8],
//   W_n1[256,256], b_n1[256], W_n2[256,256], b_n2[256] -> out[1024,256] fp32
//   Engine: mma.sync m16n8k16 FP16. Gate path: activation hi/lo 2-pass.
//   Feats path: hi-only 1-pass (drops ~2^-11 terms; measured-safe margin).
//   256-thread CTAs, 2 CTAs/SM. Structure = R13.
// ---------------------------------------------------------------------------

#define N_MAX 200000
#define MAX_TILES ((N_MAX + 63) / 64)

__device__ float g_alpha[(size_t)N_MAX * 8];    // alpha, then gates (in-place)
// fragment-ordered fp16 weights, 2 n-fragments packed per uint4:
// [w(3)][kstep(16)][nf2(16)][lane(32)] uint4 = {bj0.r0, bj0.r1, bj1.r0, bj1.r1}
__device__ uint4 g_Wfrag4[3 * 16 * 16 * 32];
// H (fp16 hi only) in A-fragment order: [tb16][kb(16)][lane(32)] uint4
__device__ uint4 g_H[(size_t)MAX_TILES * 4 * 16 * 32];

// ---------------- helpers ---------------------------------------------------
__device__ __forceinline__ uint32_t smem_u32(const void* p) {
    uint32_t a;
    asm("{ .reg .u64 t; cvta.to.shared.u64 t, %1; cvt.u32.u64 %0, t; }"
        : "=r"(a) : "l"(p));
    return a;
}
__device__ __forceinline__ void split_f16(float v, uint16_t& h, uint16_t& l) {
    __half hb = __float2half_rn(v);
    h = __half_as_ushort(hb);
    l = __half_as_ushort(__float2half_rn(v - __half2float(hb)));
}
__device__ __forceinline__ uint16_t f16(float v) {
    return __half_as_ushort(__float2half_rn(v));
}
__device__ __forceinline__ void ldsm4(uint32_t* a, uint32_t addr) {
    asm volatile("ldmatrix.sync.aligned.m8n8.x4.shared.b16 {%0,%1,%2,%3}, [%4];"
                 : "=r"(a[0]), "=r"(a[1]), "=r"(a[2]), "=r"(a[3]) : "r"(addr));
}
__device__ __forceinline__ void lds128(uint32_t* a, uint32_t addr) {
    asm volatile("ld.shared.v4.u32 {%0,%1,%2,%3}, [%4];"
                 : "=r"(a[0]), "=r"(a[1]), "=r"(a[2]), "=r"(a[3]) : "r"(addr));
}
__device__ __forceinline__ void cpasync16z(uint32_t dst, const void* src, int sz) {
    asm volatile("cp.async.cg.shared.global [%0], [%1], 16, %2;\n"
                 :: "r"(dst), "l"(src), "r"(sz) : "memory");
}
__device__ __forceinline__ void mma16816(float* c, const uint32_t* a,
                                         uint32_t b0, uint32_t b1) {
    asm volatile(
        "mma.sync.aligned.m16n8k16.row.col.f32.f16.f16.f32 "
        "{%0,%1,%2,%3},{%4,%5,%6,%7},{%8,%9},{%0,%1,%2,%3};"
        : "+f"(c[0]), "+f"(c[1]), "+f"(c[2]), "+f"(c[3])
        : "r"(a[0]), "r"(a[1]), "r"(a[2]), "r"(a[3]), "r"(b0), "r"(b1));
}

// ---------------- smem layouts (bytes) --------------------------------------
#define P_A 528                    // fp16 tile pitch (32 rows x 256 cols + pad)
// k1 (per CTA, 32 rows):
#define OFF_AH1  0                 // 16896
#define OFF_AL1  16896             // 16896
#define OFF_WG2  33792             // 8192
#define OFF_ALP  41984             // 1024 (32x8 fp32)
#define OFF_B1K  43008             // 1024
#define SMEM_K1  44032

// k2 (per CTA, 64 rows): H staging [0..32768) overlays Wf [0..66048)
#define OFF_H    0
#define P_WF 1032
#define OFF_WF   0
#define OFF_B2K  66048             // 1024
#define OFF_BBK  67072             // 256 (64 ints)
#define SMEM_K2  67328

// ---------------------------------------------------------------------------
// k_prep: pack 3 weights into fragment-pair-ordered fp16 uint4.
// ---------------------------------------------------------------------------
__global__ void k_prep(const float* __restrict__ Wn1,
                       const float* __restrict__ Wg1,
                       const float* __restrict__ Wn2)
{
    const float* W = (blockIdx.y == 0) ? Wn1 : (blockIdx.y == 1) ? Wg1 : Wn2;
    const int i = blockIdx.x * 256 + threadIdx.x;   // 0..8191
    const int lane = i & 31;
    const int nf2  = (i >> 5) & 15;
    const int ks   = i >> 9;
    const int k0   = ks * 16 + (lane & 3) * 2;

    uint4 o;
    {
        const int nn = (2 * nf2) * 8 + (lane >> 2);
        o.x = (uint32_t)f16(W[(k0 + 0) * 256 + nn]) |
              ((uint32_t)f16(W[(k0 + 1) * 256 + nn]) << 16);
        o.y = (uint32_t)f16(W[(k0 + 8) * 256 + nn]) |
              ((uint32_t)f16(W[(k0 + 9) * 256 + nn]) << 16);
    }
    {
        const int nn = (2 * nf2 + 1) * 8 + (lane >> 2);
        o.z = (uint32_t)f16(W[(k0 + 0) * 256 + nn]) |
              ((uint32_t)f16(W[(k0 + 1) * 256 + nn]) << 16);
        o.w = (uint32_t)f16(W[(k0 + 8) * 256 + nn]) |
              ((uint32_t)f16(W[(k0 + 9) * 256 + nn]) << 16);
    }
    g_Wfrag4[(((blockIdx.y * 16 + ks) * 16 + nf2) * 32) + lane] = o;
}

// ---------------------------------------------------------------------------
// k1: 32-row tile, 256 threads (8 warps). Warps nw 0..3: feats GEMM
// (hi-only 1-pass) -> H fragments to g_H. Warps nw 4..7: gate GEMM
// (hi/lo 2-pass) -> alpha = relu(D)@Wg2 -> g_alpha.
// ---------------------------------------------------------------------------
__global__ __launch_bounds__(256, 2)
void k1(const float* __restrict__ x,
        const float* __restrict__ Wg2,
        const float* __restrict__ bn1,
        int n)
{
    extern __shared__ unsigned char sm[];
    const uint32_t sb = smem_u32(sm);
    float* Wg2s     = (float*)(sm + OFF_WG2);
    float* alpha_sm = (float*)(sm + OFF_ALP);
    float* b1s      = (float*)(sm + OFF_B1K);

    const int t = threadIdx.x;
    const int lane = t & 31, nw = t >> 5;
    const int g = lane >> 2, tig = lane & 3;
    const int m0 = blockIdx.x * 32;

    #pragma unroll
    for (int q = 0; q < 8; ++q) Wg2s[t + q * 256] = Wg2[t + q * 256];
    b1s[t] = bn1[t];
    alpha_sm[t] = 0.f;

    // stage x[m0:m0+32, 0:256] -> fp16 hi/lo smem
    #pragma unroll
    for (int e = 0; e < 8; ++e) {
        const int idx = t + e * 256;            // 0..2047 float4s
        const int row = idx >> 6, q = idx & 63;
        const int m = m0 + row;
        float4 v = make_float4(0.f, 0.f, 0.f, 0.f);
        if (m < n) v = ((const float4*)(x + (size_t)m * 256))[q];
        uint16_t h0, h1, h2, h3, l0, l1, l2, l3;
        split_f16(v.x, h0, l0);
        split_f16(v.y, h1, l1);
        split_f16(v.z, h2, l2);
        split_f16(v.w, h3, l3);
        uint2 hp, lp;
        hp.x = (uint32_t)h0 | ((uint32_t)h1 << 16);
        hp.y = (uint32_t)h2 | ((uint32_t)h3 << 16);
        lp.x = (uint32_t)l0 | ((uint32_t)l1 << 16);
        lp.y = (uint32_t)l2 | ((uint32_t)l3 << 16);
        *(uint2*)(sm + OFF_AH1 + row * P_A + q * 8) = hp;
        *(uint2*)(sm + OFF_AL1 + row * P_A + q * 8) = lp;
    }
    __syncthreads();

    float acc[8][2][4];
    #pragma unroll
    for (int j = 0; j < 8; ++j)
        #pragma unroll
        for (int mf = 0; mf < 2; ++mf)
            #pragma unroll
            for (int q = 0; q < 4; ++q) acc[j][mf][q] = 0.f;

    const int nb2 = (nw & 3) * 4;   // nf2 base for this warp's 8 fragments

    if (nw < 4) {
        // ---- feats GEMM: x_hi @ Wn1 (1-pass) ----
        #pragma unroll
        for (int ks = 0; ks < 16; ++ks) {
            const uint32_t abase = sb + (lane & 15) * P_A + ks * 32 + ((lane >> 4) << 4);
            uint32_t ah0[4], ah1[4];
            ldsm4(ah0, abase + OFF_AH1);
            ldsm4(ah1, abase + OFF_AH1 + 16 * P_A);
            const int fb = ((0 * 16 + ks) * 16 + nb2) * 32 + lane;
            #pragma unroll
            for (int q = 0; q < 4; ++q) {
                const uint4 b = __ldg(&g_Wfrag4[fb + q * 32]);
                const int j0 = 2 * q, j1 = 2 * q + 1;
                mma16816(acc[j0][0], ah0, b.x, b.y);
                mma16816(acc[j0][1], ah1, b.x, b.y);
                mma16816(acc[j1][0], ah0, b.z, b.w);
                mma16816(acc[j1][1], ah1, b.z, b.w);
            }
        }
        // ---- H = relu(D + b1): fp16 hi only, A-fragment order to g_H ----
        #pragma unroll
        for (int mf = 0; mf < 2; ++mf) {
            const size_t tb = (size_t)(blockIdx.x * 2 + mf);
            #pragma unroll
            for (int kp = 0; kp < 4; ++kp) {
                const int kb = nw * 4 + kp;
                uint4 Hh;
                #pragma unroll
                for (int je = 0; je < 2; ++je) {
                    const int j = kp * 2 + je;
                    const int c = nw * 64 + j * 8 + tig * 2;
                    const uint32_t hp0 =
                        (uint32_t)f16(fmaxf(acc[j][mf][0] + b1s[c],     0.f)) |
                        ((uint32_t)f16(fmaxf(acc[j][mf][1] + b1s[c + 1], 0.f)) << 16);
                    const uint32_t hp1 =
                        (uint32_t)f16(fmaxf(acc[j][mf][2] + b1s[c],     0.f)) |
                        ((uint32_t)f16(fmaxf(acc[j][mf][3] + b1s[c + 1], 0.f)) << 16);
                    if (je == 0) { Hh.x = hp0; Hh.y = hp1; }
                    else         { Hh.z = hp0; Hh.w = hp1; }
                }
                g_H[((tb * 16 + kb)) * 32 + lane] = Hh;
            }
        }
    } else {
        // ---- gate GEMM: (x_hi + x_lo) @ Wg1 (2-pass) ----
        #pragma unroll
        for (int ks = 0; ks < 16; ++ks) {
            const uint32_t abase = sb + (lane & 15) * P_A + ks * 32 + ((lane >> 4) << 4);
            uint32_t ah0[4], ah1[4], al0[4], al1[4];
            ldsm4(ah0, abase + OFF_AH1);
            ldsm4(ah1, abase + OFF_AH1 + 16 * P_A);
            ldsm4(al0, abase + OFF_AL1);
            ldsm4(al1, abase + OFF_AL1 + 16 * P_A);
            const int fb = ((1 * 16 + ks) * 16 + nb2) * 32 + lane;
            #pragma unroll
            for (int q = 0; q < 4; ++q) {
                const uint4 b = __ldg(&g_Wfrag4[fb + q * 32]);
                const int j0 = 2 * q, j1 = 2 * q + 1;
                mma16816(acc[j0][0], ah0, b.x, b.y);
                mma16816(acc[j0][1], ah1, b.x, b.y);
                mma16816(acc[j0][0], al0, b.x, b.y);
                mma16816(acc[j0][1], al1, b.x, b.y);
                mma16816(acc[j1][0], ah0, b.z, b.w);
                mma16816(acc[j1][1], ah1, b.z, b.w);
                mma16816(acc[j1][0], al0, b.z, b.w);
                mma16816(acc[j1][1], al1, b.z, b.w);
            }
        }
        // ---- alpha partial = relu(D) @ Wg2 over this warp's 64-col slice ----
        float pa[4][8];
        #pragma unroll
        for (int s = 0; s < 4; ++s)
            #pragma unroll
            for (int h = 0; h < 8; ++h) pa[s][h] = 0.f;

        #pragma unroll
        for (int mf = 0; mf < 2; ++mf)
            #pragma unroll
            for (int j = 0; j < 8; ++j) {
                const int c = (nw - 4) * 64 + j * 8 + tig * 2;
                const float d0 = fmaxf(acc[j][mf][0], 0.f);
                const float d1 = fmaxf(acc[j][mf][1], 0.f);
                const float d2 = fmaxf(acc[j][mf][2], 0.f);
                const float d3 = fmaxf(acc[j][mf][3], 0.f);
                const float4* wa = (const float4*)(Wg2s + c * 8);
                const float4* wb = (const float4*)(Wg2s + (c + 1) * 8);
                const float4 a0 = wa[0], a1 = wa[1], b0 = wb[0], b1 = wb[1];
                float* p0 = pa[mf * 2];
                float* p1 = pa[mf * 2 + 1];
                p0[0] = fmaf(d0, a0.x, fmaf(d1, b0.x, p0[0]));
                p0[1] = fmaf(d0, a0.y, fmaf(d1, b0.y, p0[1]));
                p0[2] = fmaf(d0, a0.z, fmaf(d1, b0.z, p0[2]));
                p0[3] = fmaf(d0, a0.w, fmaf(d1, b0.w, p0[3]));
                p0[4] = fmaf(d0, a1.x, fmaf(d1, b1.x, p0[4]));
                p0[5] = fmaf(d0, a1.y, fmaf(d1, b1.y, p0[5]));
                p0[6] = fmaf(d0, a1.z, fmaf(d1, b1.z, p0[6]));
                p0[7] = fmaf(d0, a1.w, fmaf(d1, b1.w, p0[7]));
                p1[0] = fmaf(d2, a0.x, fmaf(d3, b0.x, p1[0]));
                p1[1] = fmaf(d2, a0.y, fmaf(d3, b0.y, p1[1]));
                p1[2] = fmaf(d2, a0.z, fmaf(d3, b0.z, p1[2]));
                p1[3] = fmaf(d2, a0.w, fmaf(d3, b0.w, p1[3]));
                p1[4] = fmaf(d2, a1.x, fmaf(d3, b1.x, p1[4]));
                p1[5] = fmaf(d2, a1.y, fmaf(d3, b1.y, p1[5]));
                p1[6] = fmaf(d2, a1.z, fmaf(d3, b1.z, p1[6]));
                p1[7] = fmaf(d2, a1.w, fmaf(d3, b1.w, p1[7]));
            }
        #pragma unroll
        for (int off = 1; off <= 2; off <<= 1)
            #pragma unroll
            for (int s = 0; s < 4; ++s)
                #pragma unroll
                for (int h = 0; h < 8; ++h)
                    pa[s][h] += __shfl_xor_sync(0xffffffffu, pa[s][h], off);
        if (tig == 0) {
            #pragma unroll
            for (int s = 0; s < 4; ++s) {
                const int row = (s >> 1) * 16 + (s & 1) * 8 + g;
                #pragma unroll
                for (int h = 0; h < 8; ++h)
                    atomicAdd(&alpha_sm[row * 8 + h], pa[s][h]);
            }
        }
    }
    __syncthreads();

    const int row = t >> 3, h = t & 7;
    const int m = m0 + row;
    if (m < n) g_alpha[(size_t)m * 8 + h] = alpha_sm[row * 8 + h];
}

// ---------------------------------------------------------------------------
// k_stats: per graph softmax stats; overwrite g_alpha with gates; zero out.
// ---------------------------------------------------------------------------
__global__ __launch_bounds__(256)
void k_stats(const int* __restrict__ batch,
             float* __restrict__ out,
             int n)
{
    const int b = blockIdx.x;
    const int t = threadIdx.x;

    int lo, hi;
    {
        int l = 0, r2 = n;
        while (l < r2) { int mid = (l + r2) >> 1; if (batch[mid] < b) l = mid + 1; else r2 = mid; }
        lo = l;
        r2 = n;
        while (l < r2) { int mid = (l + r2) >> 1; if (batch[mid] < b + 1) l = mid + 1; else r2 = mid; }
        hi = l;
    }

    __shared__ float red[256][8];
    __shared__ float mh[8];
    __shared__ float ih[8];

    float lm[8];
    #pragma unroll
    for (int q = 0; q < 8; ++q) lm[q] = -1e30f;
    for (int i = lo + t; i < hi; i += 256) {
        #pragma unroll
        for (int q = 0; q < 8; ++q)
            lm[q] = fmaxf(lm[q], g_alpha[(size_t)i * 8 + q]);
    }
    #pragma unroll
    for (int q = 0; q < 8; ++q) red[t][q] = lm[q];
    __syncthreads();
    for (int s2 = 128; s2 > 0; s2 >>= 1) {
        if (t < s2) {
            #pragma unroll
            for (int q = 0; q < 8; ++q)
                red[t][q] = fmaxf(red[t][q], red[t + s2][q]);
        }
        __syncthreads();
    }
    if (t < 8) mh[t] = red[0][t];
    __syncthreads();

    float m8[8];
    #pragma unroll
    for (int q = 0; q < 8; ++q) m8[q] = mh[q];

    float ls[8];
    #pragma unroll
    for (int q = 0; q < 8; ++q) ls[q] = 0.f;
    for (int i = lo + t; i < hi; i += 256) {
        #pragma unroll
        for (int q = 0; q < 8; ++q)
            ls[q] += __expf(g_alpha[(size_t)i * 8 + q] - m8[q]);
    }
    __syncthreads();
    #pragma unroll
    for (int q = 0; q < 8; ++q) red[t][q] = ls[q];
    __syncthreads();
    for (int s2 = 128; s2 > 0; s2 >>= 1) {
        if (t < s2) {
            #pragma unroll
            for (int q = 0; q < 8; ++q)
                red[t][q] += red[t + s2][q];
        }
        __syncthreads();
    }
    if (t < 8) ih[t] = 1.f / (red[0][t] + 1e-16f);
    __syncthreads();

    float i8[8];
    #pragma unroll
    for (int q = 0; q < 8; ++q) i8[q] = ih[q];

    for (long long e = (long long)lo * 8 + t; e < (long long)hi * 8; e += 256) {
        const int h = (int)(e & 7);
        g_alpha[e] = __expf(g_alpha[e] - m8[h]) * i8[h];
    }
    out[(size_t)b * 256 + t] = 0.f;
}

// ---------------------------------------------------------------------------
// k2: 64-row tile, 256 threads (8 warps). Warp tile 32x64 (mw2 = w&1,
// nw2 = w>>1). cp.async H stage (32KB); D2 = H_hi @ Wn2 (1-pass) (+b2),
// gate-weight, segmented reduce, atomics.
// ---------------------------------------------------------------------------
__global__ __launch_bounds__(256, 2)
void k2(const int* __restrict__ batch,
        const float* __restrict__ bn2,
        float* __restrict__ out,
        int n)
{
    extern __shared__ unsigned char sm[];
    const uint32_t sb = smem_u32(sm);
    float* b2s = (float*)(sm + OFF_B2K);
    int*   bbs = (int*)(sm + OFF_BBK);

    const int t = threadIdx.x;
    const int lane = t & 31, w = t >> 5;
    const int g = lane >> 2, tig = lane & 3;
    const int m0 = blockIdx.x * 64;
    const int mw2 = w & 1, nw2 = w >> 1;

    const int tbWritten = ((n + 31) / 32) * 2;

    // ---- bulk-stage this tile's H block (2048 uint4 = 32KB, zfill OOB) ----
    {
        const uint4* src = g_H + (size_t)blockIdx.x * 2048;
        #pragma unroll
        for (int e = 0; e < 8; ++e) {
            const int idx = t + e * 256;           // 0..2047
            const int tbl = idx >> 9;              // local 16-row block (512 u4)
            const int sz = (blockIdx.x * 4 + tbl < tbWritten) ? 16 : 0;
            cpasync16z(sb + OFF_H + idx * 16, src + idx, sz);
        }
        asm volatile("cp.async.commit_group;\n" ::: "memory");
    }
    b2s[t] = bn2[t];
    if (t < 64) bbs[t] = (m0 + t < n) ? batch[m0 + t] : -1;
    asm volatile("cp.async.wait_group 0;\n" ::: "memory");
    __syncthreads();

    float acc[2][8][4];
    #pragma unroll
    for (int mf = 0; mf < 2; ++mf)
        #pragma unroll
        for (int j = 0; j < 8; ++j)
            #pragma unroll
            for (int q = 0; q < 4; ++q) acc[mf][j][q] = 0.f;

    #pragma unroll
    for (int kb = 0; kb < 16; ++kb) {
        uint32_t ah0[4], ah1[4];
        const int tb0 = mw2 * 2;
        const uint32_t h0 = sb + OFF_H + (((tb0 * 16 + kb) * 32) + lane) * 16;
        const uint32_t h1 = sb + OFF_H + ((((tb0 + 1) * 16 + kb) * 32) + lane) * 16;
        lds128(ah0, h0);
        lds128(ah1, h1);
        const int fb = ((2 * 16 + kb) * 16 + nw2 * 4) * 32 + lane;
        #pragma unroll
        for (int q = 0; q < 4; ++q) {
            const uint4 b = __ldg(&g_Wfrag4[fb + q * 32]);
            const int j0 = 2 * q, j1 = 2 * q + 1;
            mma16816(acc[0][j0], ah0, b.x, b.y);
            mma16816(acc[1][j0], ah1, b.x, b.y);
            mma16816(acc[0][j1], ah0, b.z, b.w);
            mma16816(acc[1][j1], ah1, b.z, b.w);
        }
    }
    __syncthreads();   // all H reads done; Wf region overlays H

    // ---- weighted feats -> smem Wf[64][256] ----
    #pragma unroll
    for (int mf = 0; mf < 2; ++mf) {
        const int r0 = mw2 * 32 + mf * 16 + g;
        const int r1 = r0 + 8;
        float2 g0 = make_float2(0.f, 0.f), g1 = make_float2(0.f, 0.f);
        if (m0 + r0 < n) g0 = *(const float2*)(g_alpha + (size_t)(m0 + r0) * 8 + tig * 2);
        if (m0 + r1 < n) g1 = *(const float2*)(g_alpha + (size_t)(m0 + r1) * 8 + tig * 2);
        #pragma unroll
        for (int j = 0; j < 8; ++j) {
            const int c = nw2 * 64 + j * 8 + tig * 2;
            float2 s0, s1;
            s0.x = (acc[mf][j][0] + b2s[c])     * g0.x;
            s0.y = (acc[mf][j][1] + b2s[c + 1]) * g0.y;
            s1.x = (acc[mf][j][2] + b2s[c])     * g1.x;
            s1.y = (acc[mf][j][3] + b2s[c + 1]) * g1.y;
            *(float2*)(sm + OFF_WF + r0 * P_WF + c * 4) = s0;
            *(float2*)(sm + OFF_WF + r1 * P_WF + c * 4) = s1;
        }
    }
    __syncthreads();

    // ---- segmented reduction over 64 rows (sorted batch) -> atomicAdd out ----
    {
        const int c = t;
        float s = 0.f;
        int cur = -1;
        #pragma unroll 4
        for (int r = 0; r < 64; ++r) {
            if (m0 + r >= n) break;
            const int gid = bbs[r];
            if (gid != cur) {
                if (cur >= 0) atomicAdd(out + (size_t)cur * 256 + c, s);
                cur = gid;
                s = 0.f;
            }
            s += *(const float*)(sm + OFF_WF + r * P_WF + c * 4);
        }
        if (cur >= 0) atomicAdd(out + (size_t)cur * 256 + c, s);
    }
}

// ---------------------------------------------------------------------------
extern "C" void kernel_launch(void* const* d_in, const int* in_sizes, int n_in,
                              void* d_out, int out_size)
{
    const float* x     = (const float*)d_in[0];
    const int*   batch = (const int*)d_in[1];
    const float* Wg1   = (const float*)d_in[2];
    const float* Wg2   = (const float*)d_in[3];
    const float* Wn1   = (const float*)d_in[4];
    const float* bn1   = (const float*)d_in[5];
    const float* Wn2   = (const float*)d_in[6];
    const float* bn2   = (const float*)d_in[7];
    float* out = (float*)d_out;

    const int n = in_sizes[0] / 256;
    const int B = out_size / 256;
    const int tiles32 = (n + 31) / 32;
    const int tiles64 = (n + 63) / 64;

    cudaFuncSetAttribute(k1, cudaFuncAttributeMaxDynamicSharedMemorySize, SMEM_K1);
    cudaFuncSetAttribute(k2, cudaFuncAttributeMaxDynamicSharedMemorySize, SMEM_K2);

    k_prep<<<dim3(32, 3), 256>>>(Wn1, Wg1, Wn2);
    k1<<<tiles32, 256, SMEM_K1>>>(x, Wg2, bn1, n);
    k_stats<<<B, 256>>>(batch, out, n);
    k2<<<tiles64, 256, SMEM_K2>>>(batch, bn2, out, n);
}

// round 15
// speedup vs baseline: 1.8819x; 1.1050x over previous
#include <cuda_runtime.h>
#include <cuda_fp16.h>
#include <cstdint>
#include <cstddef>

// ---------------------------------------------------------------------------
//   x[N,256], batch[N] int32 sorted, W_g1[256,256], W_g2[256,8],
//   W_n1[256,256], b_n1[256], W_n2[256,256], b_n2[256] -> out[1024,256] fp32
//   Engine: mma.sync m16n8k16 FP16, 1-pass everywhere (fp16 inputs, fp32
//   accum; measured error budget dominated by weight quantization).
//   256-thread CTAs, 2 CTAs/SM. Structure = R14.
// ---------------------------------------------------------------------------

#define N_MAX 200000
#define MAX_TILES ((N_MAX + 63) / 64)

__device__ float g_alpha[(size_t)N_MAX * 8];    // alpha, then gates (in-place)
// fragment-ordered fp16 weights, 2 n-fragments packed per uint4:
// [w(3)][kstep(16)][nf2(16)][lane(32)] uint4 = {bj0.r0, bj0.r1, bj1.r0, bj1.r1}
__device__ uint4 g_Wfrag4[3 * 16 * 16 * 32];
// H (fp16) in A-fragment order: [tb16][kb(16)][lane(32)] uint4
__device__ uint4 g_H[(size_t)MAX_TILES * 4 * 16 * 32];

// ---------------- helpers ---------------------------------------------------
__device__ __forceinline__ uint32_t smem_u32(const void* p) {
    uint32_t a;
    asm("{ .reg .u64 t; cvta.to.shared.u64 t, %1; cvt.u32.u64 %0, t; }"
        : "=r"(a) : "l"(p));
    return a;
}
__device__ __forceinline__ uint16_t f16(float v) {
    return __half_as_ushort(__float2half_rn(v));
}
__device__ __forceinline__ void ldsm4(uint32_t* a, uint32_t addr) {
    asm volatile("ldmatrix.sync.aligned.m8n8.x4.shared.b16 {%0,%1,%2,%3}, [%4];"
                 : "=r"(a[0]), "=r"(a[1]), "=r"(a[2]), "=r"(a[3]) : "r"(addr));
}
__device__ __forceinline__ void lds128(uint32_t* a, uint32_t addr) {
    asm volatile("ld.shared.v4.u32 {%0,%1,%2,%3}, [%4];"
                 : "=r"(a[0]), "=r"(a[1]), "=r"(a[2]), "=r"(a[3]) : "r"(addr));
}
__device__ __forceinline__ void cpasync16z(uint32_t dst, const void* src, int sz) {
    asm volatile("cp.async.cg.shared.global [%0], [%1], 16, %2;\n"
                 :: "r"(dst), "l"(src), "r"(sz) : "memory");
}
__device__ __forceinline__ void mma16816(float* c, const uint32_t* a,
                                         uint32_t b0, uint32_t b1) {
    asm volatile(
        "mma.sync.aligned.m16n8k16.row.col.f32.f16.f16.f32 "
        "{%0,%1,%2,%3},{%4,%5,%6,%7},{%8,%9},{%0,%1,%2,%3};"
        : "+f"(c[0]), "+f"(c[1]), "+f"(c[2]), "+f"(c[3])
        : "r"(a[0]), "r"(a[1]), "r"(a[2]), "r"(a[3]), "r"(b0), "r"(b1));
}

// ---------------- smem layouts (bytes) --------------------------------------
#define P_A 528                    // fp16 tile pitch (32 rows x 256 cols + pad)
// k1 (per CTA, 32 rows):
#define OFF_AH1  0                 // 16896
#define OFF_WG2  16896             // 8192
#define OFF_ALP  25088             // 1024 (32x8 fp32)
#define OFF_B1K  26112             // 1024
#define SMEM_K1  27136

// k2 (per CTA, 64 rows): H staging [0..32768) overlays Wf [0..66048)
#define OFF_H    0
#define P_WF 1032
#define OFF_WF   0
#define OFF_B2K  66048             // 1024
#define OFF_BBK  67072             // 256 (64 ints)
#define SMEM_K2  67328

// ---------------------------------------------------------------------------
// k_prep: pack 3 weights into fragment-pair-ordered fp16 uint4.
// ---------------------------------------------------------------------------
__global__ void k_prep(const float* __restrict__ Wn1,
                       const float* __restrict__ Wg1,
                       const float* __restrict__ Wn2)
{
    const float* W = (blockIdx.y == 0) ? Wn1 : (blockIdx.y == 1) ? Wg1 : Wn2;
    const int i = blockIdx.x * 256 + threadIdx.x;   // 0..8191
    const int lane = i & 31;
    const int nf2  = (i >> 5) & 15;
    const int ks   = i >> 9;
    const int k0   = ks * 16 + (lane & 3) * 2;

    uint4 o;
    {
        const int nn = (2 * nf2) * 8 + (lane >> 2);
        o.x = (uint32_t)f16(W[(k0 + 0) * 256 + nn]) |
              ((uint32_t)f16(W[(k0 + 1) * 256 + nn]) << 16);
        o.y = (uint32_t)f16(W[(k0 + 8) * 256 + nn]) |
              ((uint32_t)f16(W[(k0 + 9) * 256 + nn]) << 16);
    }
    {
        const int nn = (2 * nf2 + 1) * 8 + (lane >> 2);
        o.z = (uint32_t)f16(W[(k0 + 0) * 256 + nn]) |
              ((uint32_t)f16(W[(k0 + 1) * 256 + nn]) << 16);
        o.w = (uint32_t)f16(W[(k0 + 8) * 256 + nn]) |
              ((uint32_t)f16(W[(k0 + 9) * 256 + nn]) << 16);
    }
    g_Wfrag4[(((blockIdx.y * 16 + ks) * 16 + nf2) * 32) + lane] = o;
}

// ---------------------------------------------------------------------------
// k1: 32-row tile, 256 threads (8 warps). 1-pass fp16 GEMM vs image
// (nw<4 -> Wn1/feats; nw>=4 -> Wg1/gate). Feats warps -> H frags to g_H;
// gate warps -> alpha = relu(D)@Wg2 -> g_alpha.
// ---------------------------------------------------------------------------
__global__ __launch_bounds__(256, 2)
void k1(const float* __restrict__ x,
        const float* __restrict__ Wg2,
        const float* __restrict__ bn1,
        int n)
{
    extern __shared__ unsigned char sm[];
    const uint32_t sb = smem_u32(sm);
    float* Wg2s     = (float*)(sm + OFF_WG2);
    float* alpha_sm = (float*)(sm + OFF_ALP);
    float* b1s      = (float*)(sm + OFF_B1K);

    const int t = threadIdx.x;
    const int lane = t & 31, nw = t >> 5;
    const int g = lane >> 2, tig = lane & 3;
    const int m0 = blockIdx.x * 32;

    #pragma unroll
    for (int q = 0; q < 8; ++q) Wg2s[t + q * 256] = Wg2[t + q * 256];
    b1s[t] = bn1[t];
    alpha_sm[t] = 0.f;

    // stage x[m0:m0+32, 0:256] -> fp16 smem
    #pragma unroll
    for (int e = 0; e < 8; ++e) {
        const int idx = t + e * 256;            // 0..2047 float4s
        const int row = idx >> 6, q = idx & 63;
        const int m = m0 + row;
        float4 v = make_float4(0.f, 0.f, 0.f, 0.f);
        if (m < n) v = ((const float4*)(x + (size_t)m * 256))[q];
        uint2 hp;
        hp.x = (uint32_t)f16(v.x) | ((uint32_t)f16(v.y) << 16);
        hp.y = (uint32_t)f16(v.z) | ((uint32_t)f16(v.w) << 16);
        *(uint2*)(sm + OFF_AH1 + row * P_A + q * 8) = hp;
    }
    __syncthreads();

    float acc[8][2][4];
    #pragma unroll
    for (int j = 0; j < 8; ++j)
        #pragma unroll
        for (int mf = 0; mf < 2; ++mf)
            #pragma unroll
            for (int q = 0; q < 4; ++q) acc[j][mf][q] = 0.f;

    const int img = (nw >= 4) ? 1 : 0;
    const int nb2 = (nw & 3) * 4;   // nf2 base for this warp's 8 fragments

    #pragma unroll
    for (int ks = 0; ks < 16; ++ks) {
        const uint32_t abase = sb + (lane & 15) * P_A + ks * 32 + ((lane >> 4) << 4);
        uint32_t ah0[4], ah1[4];
        ldsm4(ah0, abase + OFF_AH1);
        ldsm4(ah1, abase + OFF_AH1 + 16 * P_A);
        const int fb = ((img * 16 + ks) * 16 + nb2) * 32 + lane;
        #pragma unroll
        for (int q = 0; q < 4; ++q) {
            const uint4 b = __ldg(&g_Wfrag4[fb + q * 32]);
            const int j0 = 2 * q, j1 = 2 * q + 1;
            mma16816(acc[j0][0], ah0, b.x, b.y);
            mma16816(acc[j0][1], ah1, b.x, b.y);
            mma16816(acc[j1][0], ah0, b.z, b.w);
            mma16816(acc[j1][1], ah1, b.z, b.w);
        }
    }

    if (nw < 4) {
        // ---- H = relu(D + b1): fp16, A-fragment order to g_H ----
        #pragma unroll
        for (int mf = 0; mf < 2; ++mf) {
            const size_t tb = (size_t)(blockIdx.x * 2 + mf);
            #pragma unroll
            for (int kp = 0; kp < 4; ++kp) {
                const int kb = nw * 4 + kp;
                uint4 Hh;
                #pragma unroll
                for (int je = 0; je < 2; ++je) {
                    const int j = kp * 2 + je;
                    const int c = nw * 64 + j * 8 + tig * 2;
                    const uint32_t hp0 =
                        (uint32_t)f16(fmaxf(acc[j][mf][0] + b1s[c],     0.f)) |
                        ((uint32_t)f16(fmaxf(acc[j][mf][1] + b1s[c + 1], 0.f)) << 16);
                    const uint32_t hp1 =
                        (uint32_t)f16(fmaxf(acc[j][mf][2] + b1s[c],     0.f)) |
                        ((uint32_t)f16(fmaxf(acc[j][mf][3] + b1s[c + 1], 0.f)) << 16);
                    if (je == 0) { Hh.x = hp0; Hh.y = hp1; }
                    else         { Hh.z = hp0; Hh.w = hp1; }
                }
                g_H[((tb * 16 + kb)) * 32 + lane] = Hh;
            }
        }
    } else {
        // ---- alpha partial = relu(D) @ Wg2 over this warp's 64-col slice ----
        float pa[4][8];
        #pragma unroll
        for (int s = 0; s < 4; ++s)
            #pragma unroll
            for (int h = 0; h < 8; ++h) pa[s][h] = 0.f;

        #pragma unroll
        for (int mf = 0; mf < 2; ++mf)
            #pragma unroll
            for (int j = 0; j < 8; ++j) {
                const int c = (nw - 4) * 64 + j * 8 + tig * 2;
                const float d0 = fmaxf(acc[j][mf][0], 0.f);
                const float d1 = fmaxf(acc[j][mf][1], 0.f);
                const float d2 = fmaxf(acc[j][mf][2], 0.f);
                const float d3 = fmaxf(acc[j][mf][3], 0.f);
                const float4* wa = (const float4*)(Wg2s + c * 8);
                const float4* wb = (const float4*)(Wg2s + (c + 1) * 8);
                const float4 a0 = wa[0], a1 = wa[1], b0 = wb[0], b1 = wb[1];
                float* p0 = pa[mf * 2];
                float* p1 = pa[mf * 2 + 1];
                p0[0] = fmaf(d0, a0.x, fmaf(d1, b0.x, p0[0]));
                p0[1] = fmaf(d0, a0.y, fmaf(d1, b0.y, p0[1]));
                p0[2] = fmaf(d0, a0.z, fmaf(d1, b0.z, p0[2]));
                p0[3] = fmaf(d0, a0.w, fmaf(d1, b0.w, p0[3]));
                p0[4] = fmaf(d0, a1.x, fmaf(d1, b1.x, p0[4]));
                p0[5] = fmaf(d0, a1.y, fmaf(d1, b1.y, p0[5]));
                p0[6] = fmaf(d0, a1.z, fmaf(d1, b1.z, p0[6]));
                p0[7] = fmaf(d0, a1.w, fmaf(d1, b1.w, p0[7]));
                p1[0] = fmaf(d2, a0.x, fmaf(d3, b0.x, p1[0]));
                p1[1] = fmaf(d2, a0.y, fmaf(d3, b0.y, p1[1]));
                p1[2] = fmaf(d2, a0.z, fmaf(d3, b0.z, p1[2]));
                p1[3] = fmaf(d2, a0.w, fmaf(d3, b0.w, p1[3]));
                p1[4] = fmaf(d2, a1.x, fmaf(d3, b1.x, p1[4]));
                p1[5] = fmaf(d2, a1.y, fmaf(d3, b1.y, p1[5]));
                p1[6] = fmaf(d2, a1.z, fmaf(d3, b1.z, p1[6]));
                p1[7] = fmaf(d2, a1.w, fmaf(d3, b1.w, p1[7]));
            }
        #pragma unroll
        for (int off = 1; off <= 2; off <<= 1)
            #pragma unroll
            for (int s = 0; s < 4; ++s)
                #pragma unroll
                for (int h = 0; h < 8; ++h)
                    pa[s][h] += __shfl_xor_sync(0xffffffffu, pa[s][h], off);
        if (tig == 0) {
            #pragma unroll
            for (int s = 0; s < 4; ++s) {
                const int row = (s >> 1) * 16 + (s & 1) * 8 + g;
                #pragma unroll
                for (int h = 0; h < 8; ++h)
                    atomicAdd(&alpha_sm[row * 8 + h], pa[s][h]);
            }
        }
    }
    __syncthreads();

    const int row = t >> 3, h = t & 7;
    const int m = m0 + row;
    if (m < n) g_alpha[(size_t)m * 8 + h] = alpha_sm[row * 8 + h];
}

// ---------------------------------------------------------------------------
// k_stats: per graph softmax stats; overwrite g_alpha with gates; zero out.
// ---------------------------------------------------------------------------
__global__ __launch_bounds__(256)
void k_stats(const int* __restrict__ batch,
             float* __restrict__ out,
             int n)
{
    const int b = blockIdx.x;
    const int t = threadIdx.x;

    int lo, hi;
    {
        int l = 0, r2 = n;
        while (l < r2) { int mid = (l + r2) >> 1; if (batch[mid] < b) l = mid + 1; else r2 = mid; }
        lo = l;
        r2 = n;
        while (l < r2) { int mid = (l + r2) >> 1; if (batch[mid] < b + 1) l = mid + 1; else r2 = mid; }
        hi = l;
    }

    __shared__ float red[256][8];
    __shared__ float mh[8];
    __shared__ float ih[8];

    float lm[8];
    #pragma unroll
    for (int q = 0; q < 8; ++q) lm[q] = -1e30f;
    for (int i = lo + t; i < hi; i += 256) {
        #pragma unroll
        for (int q = 0; q < 8; ++q)
            lm[q] = fmaxf(lm[q], g_alpha[(size_t)i * 8 + q]);
    }
    #pragma unroll
    for (int q = 0; q < 8; ++q) red[t][q] = lm[q];
    __syncthreads();
    for (int s2 = 128; s2 > 0; s2 >>= 1) {
        if (t < s2) {
            #pragma unroll
            for (int q = 0; q < 8; ++q)
                red[t][q] = fmaxf(red[t][q], red[t + s2][q]);
        }
        __syncthreads();
    }
    if (t < 8) mh[t] = red[0][t];
    __syncthreads();

    float m8[8];
    #pragma unroll
    for (int q = 0; q < 8; ++q) m8[q] = mh[q];

    float ls[8];
    #pragma unroll
    for (int q = 0; q < 8; ++q) ls[q] = 0.f;
    for (int i = lo + t; i < hi; i += 256) {
        #pragma unroll
        for (int q = 0; q < 8; ++q)
            ls[q] += __expf(g_alpha[(size_t)i * 8 + q] - m8[q]);
    }
    __syncthreads();
    #pragma unroll
    for (int q = 0; q < 8; ++q) red[t][q] = ls[q];
    __syncthreads();
    for (int s2 = 128; s2 > 0; s2 >>= 1) {
        if (t < s2) {
            #pragma unroll
            for (int q = 0; q < 8; ++q)
                red[t][q] += red[t + s2][q];
        }
        __syncthreads();
    }
    if (t < 8) ih[t] = 1.f / (red[0][t] + 1e-16f);
    __syncthreads();

    float i8[8];
    #pragma unroll
    for (int q = 0; q < 8; ++q) i8[q] = ih[q];

    for (long long e = (long long)lo * 8 + t; e < (long long)hi * 8; e += 256) {
        const int h = (int)(e & 7);
        g_alpha[e] = __expf(g_alpha[e] - m8[h]) * i8[h];
    }
    out[(size_t)b * 256 + t] = 0.f;
}

// ---------------------------------------------------------------------------
// k2: 64-row tile, 256 threads (8 warps). Warp tile 32x64 (mw2 = w&1,
// nw2 = w>>1). cp.async H stage (32KB); D2 = H @ Wn2 (1-pass) (+b2),
// gate-weight, segmented reduce, atomics.
// ---------------------------------------------------------------------------
__global__ __launch_bounds__(256, 2)
void k2(const int* __restrict__ batch,
        const float* __restrict__ bn2,
        float* __restrict__ out,
        int n)
{
    extern __shared__ unsigned char sm[];
    const uint32_t sb = smem_u32(sm);
    float* b2s = (float*)(sm + OFF_B2K);
    int*   bbs = (int*)(sm + OFF_BBK);

    const int t = threadIdx.x;
    const int lane = t & 31, w = t >> 5;
    const int g = lane >> 2, tig = lane & 3;
    const int m0 = blockIdx.x * 64;
    const int mw2 = w & 1, nw2 = w >> 1;

    const int tbWritten = ((n + 31) / 32) * 2;

    // ---- bulk-stage this tile's H block (2048 uint4 = 32KB, zfill OOB) ----
    {
        const uint4* src = g_H + (size_t)blockIdx.x * 2048;
        #pragma unroll
        for (int e = 0; e < 8; ++e) {
            const int idx = t + e * 256;           // 0..2047
            const int tbl = idx >> 9;              // local 16-row block (512 u4)
            const int sz = (blockIdx.x * 4 + tbl < tbWritten) ? 16 : 0;
            cpasync16z(sb + OFF_H + idx * 16, src + idx, sz);
        }
        asm volatile("cp.async.commit_group;\n" ::: "memory");
    }
    b2s[t] = bn2[t];
    if (t < 64) bbs[t] = (m0 + t < n) ? batch[m0 + t] : -1;
    asm volatile("cp.async.wait_group 0;\n" ::: "memory");
    __syncthreads();

    float acc[2][8][4];
    #pragma unroll
    for (int mf = 0; mf < 2; ++mf)
        #pragma unroll
        for (int j = 0; j < 8; ++j)
            #pragma unroll
            for (int q = 0; q < 4; ++q) acc[mf][j][q] = 0.f;

    #pragma unroll
    for (int kb = 0; kb < 16; ++kb) {
        uint32_t ah0[4], ah1[4];
        const int tb0 = mw2 * 2;
        const uint32_t h0 = sb + OFF_H + (((tb0 * 16 + kb) * 32) + lane) * 16;
        const uint32_t h1 = sb + OFF_H + ((((tb0 + 1) * 16 + kb) * 32) + lane) * 16;
        lds128(ah0, h0);
        lds128(ah1, h1);
        const int fb = ((2 * 16 + kb) * 16 + nw2 * 4) * 32 + lane;
        #pragma unroll
        for (int q = 0; q < 4; ++q) {
            const uint4 b = __ldg(&g_Wfrag4[fb + q * 32]);
            const int j0 = 2 * q, j1 = 2 * q + 1;
            mma16816(acc[0][j0], ah0, b.x, b.y);
            mma16816(acc[1][j0], ah1, b.x, b.y);
            mma16816(acc[0][j1], ah0, b.z, b.w);
            mma16816(acc[1][j1], ah1, b.z, b.w);
        }
    }
    __syncthreads();   // all H reads done; Wf region overlays H

    // ---- weighted feats -> smem Wf[64][256] ----
    #pragma unroll
    for (int mf = 0; mf < 2; ++mf) {
        const int r0 = mw2 * 32 + mf * 16 + g;
        const int r1 = r0 + 8;
        float2 g0 = make_float2(0.f, 0.f), g1 = make_float2(0.f, 0.f);
        if (m0 + r0 < n) g0 = *(const float2*)(g_alpha + (size_t)(m0 + r0) * 8 + tig * 2);
        if (m0 + r1 < n) g1 = *(const float2*)(g_alpha + (size_t)(m0 + r1) * 8 + tig * 2);
        #pragma unroll
        for (int j = 0; j < 8; ++j) {
            const int c = nw2 * 64 + j * 8 + tig * 2;
            float2 s0, s1;
            s0.x = (acc[mf][j][0] + b2s[c])     * g0.x;
            s0.y = (acc[mf][j][1] + b2s[c + 1]) * g0.y;
            s1.x = (acc[mf][j][2] + b2s[c])     * g1.x;
            s1.y = (acc[mf][j][3] + b2s[c + 1]) * g1.y;
            *(float2*)(sm + OFF_WF + r0 * P_WF + c * 4) = s0;
            *(float2*)(sm + OFF_WF + r1 * P_WF + c * 4) = s1;
        }
    }
    __syncthreads();

    // ---- segmented reduction over 64 rows (sorted batch) -> atomicAdd out ----
    {
        const int c = t;
        float s = 0.f;
        int cur = -1;
        #pragma unroll 4
        for (int r = 0; r < 64; ++r) {
            if (m0 + r >= n) break;
            const int gid = bbs[r];
            if (gid != cur) {
                if (cur >= 0) atomicAdd(out + (size_t)cur * 256 + c, s);
                cur = gid;
                s = 0.f;
            }
            s += *(const float*)(sm + OFF_WF + r * P_WF + c * 4);
        }
        if (cur >= 0) atomicAdd(out + (size_t)cur * 256 + c, s);
    }
}

// ---------------------------------------------------------------------------
extern "C" void kernel_launch(void* const* d_in, const int* in_sizes, int n_in,
                              void* d_out, int out_size)
{
    const float* x     = (const float*)d_in[0];
    const int*   batch = (const int*)d_in[1];
    const float* Wg1   = (const float*)d_in[2];
    const float* Wg2   = (const float*)d_in[3];
    const float* Wn1   = (const float*)d_in[4];
    const float* bn1   = (const float*)d_in[5];
    const float* Wn2   = (const float*)d_in[6];
    const float* bn2   = (const float*)d_in[7];
    float* out = (float*)d_out;

    const int n = in_sizes[0] / 256;
    const int B = out_size / 256;
    const int tiles32 = (n + 31) / 32;
    const int tiles64 = (n + 63) / 64;

    cudaFuncSetAttribute(k1, cudaFuncAttributeMaxDynamicSharedMemorySize, SMEM_K1);
    cudaFuncSetAttribute(k2, cudaFuncAttributeMaxDynamicSharedMemorySize, SMEM_K2);

    k_prep<<<dim3(32, 3), 256>>>(Wn1, Wg1, Wn2);
    k1<<<tiles32, 256, SMEM_K1>>>(x, Wg2, bn1, n);
    k_stats<<<B, 256>>>(batch, out, n);
    k2<<<tiles64, 256, SMEM_K2>>>(batch, bn2, out, n);
}

// round 16
// speedup vs baseline: 2.1434x; 1.1390x over previous
#include <cuda_runtime.h>
#include <cuda_fp16.h>
#include <cstdint>
#include <cstddef>

// ---------------------------------------------------------------------------
//   x[N,256], batch[N] int32 sorted, W_g1[256,256], W_g2[256,8],
//   W_n1[256,256], b_n1[256], W_n2[256,256], b_n2[256] -> out[1024,256] fp32
//   Engine: mma.sync m16n8k16 FP16 1-pass, fp32 accum. FULLY FUSED:
//   one CTA per 64-row tile does gate GEMM -> exp(alpha) (unnormalized,
//   max-sub cancels), feats GEMM -> H (smem), H GEMM -> F, exp-weighted
//   segmented reduce -> atomicAdd out + ssum. k_norm divides at the end.
//   256-thread CTAs, 2 CTAs/SM.
// ---------------------------------------------------------------------------

// fragment-ordered fp16 weights, 2 n-fragments packed per uint4:
// [w(3)][kstep(16)][nf2(16)][lane(32)] uint4  (img 0=Wn1, 1=Wg1, 2=Wn2)
__device__ uint4 g_Wfrag4[3 * 16 * 16 * 32];
__device__ float g_ssum[1024 * 8];   // per-graph per-head sum of exp(alpha)

// ---------------- helpers ---------------------------------------------------
__device__ __forceinline__ uint32_t smem_u32(const void* p) {
    uint32_t a;
    asm("{ .reg .u64 t; cvta.to.shared.u64 t, %1; cvt.u32.u64 %0, t; }"
        : "=r"(a) : "l"(p));
    return a;
}
__device__ __forceinline__ uint16_t f16(float v) {
    return __half_as_ushort(__float2half_rn(v));
}
__device__ __forceinline__ void ldsm4(uint32_t* a, uint32_t addr) {
    asm volatile("ldmatrix.sync.aligned.m8n8.x4.shared.b16 {%0,%1,%2,%3}, [%4];"
                 : "=r"(a[0]), "=r"(a[1]), "=r"(a[2]), "=r"(a[3]) : "r"(addr));
}
__device__ __forceinline__ void mma16816(float* c, const uint32_t* a,
                                         uint32_t b0, uint32_t b1) {
    asm volatile(
        "mma.sync.aligned.m16n8k16.row.col.f32.f16.f16.f32 "
        "{%0,%1,%2,%3},{%4,%5,%6,%7},{%8,%9},{%0,%1,%2,%3};"
        : "+f"(c[0]), "+f"(c[1]), "+f"(c[2]), "+f"(c[3])
        : "r"(a[0]), "r"(a[1]), "r"(a[2]), "r"(a[3]), "r"(b0), "r"(b1));
}

// ---------------- smem layout (bytes) ----------------------------------------
#define P_A 528                    // fp16 tile pitch (64 rows x 256 cols + pad)
#define OFF_X    0                 // 64*528 = 33792  (x fp16)
#define OFF_H    33792             // 33792           (H fp16)
#define P_WF 1032
#define OFF_WF   0                 // 66048, overlays X+H after GEMM2 reads
#define OFF_WG2  67584             // 8192
#define OFF_ALP  75776             // 2048 (64x8 fp32)
#define OFF_AE   77824             // 2048 (64x8 fp32 exp(alpha))
#define OFF_B1   79872             // 1024
#define OFF_B2   80896             // 1024
#define OFF_BB   81920             // 256 (64 ints)
#define SMEM_MAIN 82176

// ---------------------------------------------------------------------------
// k_prep: pack 3 weights into fragment-pair-ordered fp16 uint4;
// zero out[] and g_ssum (atomic targets).
// ---------------------------------------------------------------------------
__global__ void k_prep(const float* __restrict__ Wn1,
                       const float* __restrict__ Wg1,
                       const float* __restrict__ Wn2,
                       float* __restrict__ out, int out_elems)
{
    const float* W = (blockIdx.y == 0) ? Wn1 : (blockIdx.y == 1) ? Wg1 : Wn2;
    const int i = blockIdx.x * 256 + threadIdx.x;   // 0..8191
    const int lane = i & 31;
    const int nf2  = (i >> 5) & 15;
    const int ks   = i >> 9;
    const int k0   = ks * 16 + (lane & 3) * 2;

    uint4 o;
    {
        const int nn = (2 * nf2) * 8 + (lane >> 2);
        o.x = (uint32_t)f16(W[(k0 + 0) * 256 + nn]) |
              ((uint32_t)f16(W[(k0 + 1) * 256 + nn]) << 16);
        o.y = (uint32_t)f16(W[(k0 + 8) * 256 + nn]) |
              ((uint32_t)f16(W[(k0 + 9) * 256 + nn]) << 16);
    }
    {
        const int nn = (2 * nf2 + 1) * 8 + (lane >> 2);
        o.z = (uint32_t)f16(W[(k0 + 0) * 256 + nn]) |
              ((uint32_t)f16(W[(k0 + 1) * 256 + nn]) << 16);
        o.w = (uint32_t)f16(W[(k0 + 8) * 256 + nn]) |
              ((uint32_t)f16(W[(k0 + 9) * 256 + nn]) << 16);
    }
    g_Wfrag4[(((blockIdx.y * 16 + ks) * 16 + nf2) * 32) + lane] = o;

    // zero out[] and g_ssum
    const int gid = (blockIdx.y * gridDim.x + blockIdx.x) * 256 + threadIdx.x;
    const int tot = gridDim.x * gridDim.y * 256;
    for (int e = gid; e < out_elems; e += tot) out[e] = 0.f;
    for (int e = gid; e < 1024 * 8; e += tot) g_ssum[e] = 0.f;
}

// ---------------------------------------------------------------------------
// GEMM phase: D[64,256] = A(smem, pitch P_A, fp16) @ W_img^T.
// Warp tile 32x64: mw = w&1 (rows mw*32), nw = w>>1 (cols nw*64).
// acc[j 0..7][mf 0..1][4]: rows mw*32+mf*16+{g,g+8}, cols nw*64+j*8+tig*2(+1).
// ---------------------------------------------------------------------------
__device__ __forceinline__ void gemm_phase(uint32_t sb, int offA, int img,
                                           int mw, int nw, int lane,
                                           float (&acc)[8][2][4])
{
    #pragma unroll
    for (int j = 0; j < 8; ++j)
        #pragma unroll
        for (int mf = 0; mf < 2; ++mf)
            #pragma unroll
            for (int q = 0; q < 4; ++q) acc[j][mf][q] = 0.f;

    #pragma unroll
    for (int ks = 0; ks < 16; ++ks) {
        const uint32_t abase = sb + offA + (mw * 32 + (lane & 15)) * P_A
                               + ks * 32 + ((lane >> 4) << 4);
        uint32_t ah0[4], ah1[4];
        ldsm4(ah0, abase);
        ldsm4(ah1, abase + 16 * P_A);
        const int fb = ((img * 16 + ks) * 16 + nw * 4) * 32 + lane;
        #pragma unroll
        for (int q = 0; q < 4; ++q) {
            const uint4 b = __ldg(&g_Wfrag4[fb + q * 32]);
            const int j0 = 2 * q, j1 = 2 * q + 1;
            mma16816(acc[j0][0], ah0, b.x, b.y);
            mma16816(acc[j0][1], ah1, b.x, b.y);
            mma16816(acc[j1][0], ah0, b.z, b.w);
            mma16816(acc[j1][1], ah1, b.z, b.w);
        }
    }
}

// ---------------------------------------------------------------------------
// k_main: fully fused per 64-row tile.
// ---------------------------------------------------------------------------
__global__ __launch_bounds__(256, 2)
void k_main(const float* __restrict__ x,
            const float* __restrict__ Wg2,
            const float* __restrict__ bn1,
            const float* __restrict__ bn2,
            const int* __restrict__ batch,
            float* __restrict__ out,
            int n)
{
    extern __shared__ unsigned char sm[];
    const uint32_t sb = smem_u32(sm);
    float* Wg2s     = (float*)(sm + OFF_WG2);
    float* alpha_sm = (float*)(sm + OFF_ALP);
    float* AE       = (float*)(sm + OFF_AE);
    float* b1s      = (float*)(sm + OFF_B1);
    float* b2s      = (float*)(sm + OFF_B2);
    int*   bbs      = (int*)(sm + OFF_BB);

    const int t = threadIdx.x;
    const int lane = t & 31, w = t >> 5;
    const int g = lane >> 2, tig = lane & 3;
    const int m0 = blockIdx.x * 64;
    const int mw = w & 1, nw = w >> 1;

    #pragma unroll
    for (int q = 0; q < 8; ++q) Wg2s[t + q * 256] = Wg2[t + q * 256];
    b1s[t] = bn1[t];
    b2s[t] = bn2[t];
    if (t < 64) bbs[t] = (m0 + t < n) ? batch[m0 + t] : -1;
    alpha_sm[t] = 0.f;
    alpha_sm[t + 256] = 0.f;

    // ---- stage x[m0:m0+64, 0:256] -> fp16 smem ----
    #pragma unroll
    for (int e = 0; e < 16; ++e) {
        const int idx = t + e * 256;            // 0..4095 float4s
        const int row = idx >> 6, q = idx & 63;
        const int m = m0 + row;
        float4 v = make_float4(0.f, 0.f, 0.f, 0.f);
        if (m < n) v = ((const float4*)(x + (size_t)m * 256))[q];
        uint2 hp;
        hp.x = (uint32_t)f16(v.x) | ((uint32_t)f16(v.y) << 16);
        hp.y = (uint32_t)f16(v.z) | ((uint32_t)f16(v.w) << 16);
        *(uint2*)(sm + OFF_X + row * P_A + q * 8) = hp;
    }
    __syncthreads();

    float acc[8][2][4];

    // ================= phase 1: Dg = x @ Wg1 (img 1) =================
    gemm_phase(sb, OFF_X, 1, mw, nw, lane, acc);

    // ---- alpha partial = relu(Dg) @ Wg2 over this warp's 64-col slice ----
    {
        float pa[4][8];
        #pragma unroll
        for (int s = 0; s < 4; ++s)
            #pragma unroll
            for (int h = 0; h < 8; ++h) pa[s][h] = 0.f;

        #pragma unroll
        for (int mf = 0; mf < 2; ++mf)
            #pragma unroll
            for (int j = 0; j < 8; ++j) {
                const int c = nw * 64 + j * 8 + tig * 2;
                const float d0 = fmaxf(acc[j][mf][0], 0.f);
                const float d1 = fmaxf(acc[j][mf][1], 0.f);
                const float d2 = fmaxf(acc[j][mf][2], 0.f);
                const float d3 = fmaxf(acc[j][mf][3], 0.f);
                const float4* wa = (const float4*)(Wg2s + c * 8);
                const float4* wb = (const float4*)(Wg2s + (c + 1) * 8);
                const float4 a0 = wa[0], a1 = wa[1], b0 = wb[0], b1 = wb[1];
                float* p0 = pa[mf * 2];
                float* p1 = pa[mf * 2 + 1];
                p0[0] = fmaf(d0, a0.x, fmaf(d1, b0.x, p0[0]));
                p0[1] = fmaf(d0, a0.y, fmaf(d1, b0.y, p0[1]));
                p0[2] = fmaf(d0, a0.z, fmaf(d1, b0.z, p0[2]));
                p0[3] = fmaf(d0, a0.w, fmaf(d1, b0.w, p0[3]));
                p0[4] = fmaf(d0, a1.x, fmaf(d1, b1.x, p0[4]));
                p0[5] = fmaf(d0, a1.y, fmaf(d1, b1.y, p0[5]));
                p0[6] = fmaf(d0, a1.z, fmaf(d1, b1.z, p0[6]));
                p0[7] = fmaf(d0, a1.w, fmaf(d1, b1.w, p0[7]));
                p1[0] = fmaf(d2, a0.x, fmaf(d3, b0.x, p1[0]));
                p1[1] = fmaf(d2, a0.y, fmaf(d3, b0.y, p1[1]));
                p1[2] = fmaf(d2, a0.z, fmaf(d3, b0.z, p1[2]));
                p1[3] = fmaf(d2, a0.w, fmaf(d3, b0.w, p1[3]));
                p1[4] = fmaf(d2, a1.x, fmaf(d3, b1.x, p1[4]));
                p1[5] = fmaf(d2, a1.y, fmaf(d3, b1.y, p1[5]));
                p1[6] = fmaf(d2, a1.z, fmaf(d3, b1.z, p1[6]));
                p1[7] = fmaf(d2, a1.w, fmaf(d3, b1.w, p1[7]));
            }
        #pragma unroll
        for (int off = 1; off <= 2; off <<= 1)
            #pragma unroll
            for (int s = 0; s < 4; ++s)
                #pragma unroll
                for (int h = 0; h < 8; ++h)
                    pa[s][h] += __shfl_xor_sync(0xffffffffu, pa[s][h], off);
        if (tig == 0) {
            #pragma unroll
            for (int s = 0; s < 4; ++s) {
                const int row = mw * 32 + (s >> 1) * 16 + (s & 1) * 8 + g;
                #pragma unroll
                for (int h = 0; h < 8; ++h)
                    atomicAdd(&alpha_sm[row * 8 + h], pa[s][h]);
            }
        }
    }
    __syncthreads();

    // ---- AE = exp(alpha) (unnormalized softmax numerator) ----
    #pragma unroll
    for (int e = 0; e < 2; ++e) {
        const int idx = t + e * 256;            // (row,h) pairs, 512 total
        AE[idx] = __expf(alpha_sm[idx]);
    }
    __syncthreads();

    // ---- ssum: segmented per-graph/head sum of AE -> global atomics ----
    if (t < 16) {
        const int h = t & 7, half = t >> 3;
        float s = 0.f;
        int cur = -1;
        for (int r = half * 32; r < half * 32 + 32; ++r) {
            const int gid = bbs[r];
            if (gid != cur) {
                if (cur >= 0) atomicAdd(&g_ssum[cur * 8 + h], s);
                cur = gid;
                s = 0.f;
            }
            if (gid >= 0) s += AE[r * 8 + h];
        }
        if (cur >= 0) atomicAdd(&g_ssum[cur * 8 + h], s);
    }

    // ================= phase 2: Dn = x @ Wn1 (img 0) =================
    gemm_phase(sb, OFF_X, 0, mw, nw, lane, acc);

    // ---- H = relu(Dn + b1) -> fp16 smem (row-major, pitch P_A) ----
    #pragma unroll
    for (int mf = 0; mf < 2; ++mf) {
        const int r0 = mw * 32 + mf * 16 + g;
        const int r1 = r0 + 8;
        #pragma unroll
        for (int j = 0; j < 8; ++j) {
            const int c = nw * 64 + j * 8 + tig * 2;
            const uint32_t h0 =
                (uint32_t)f16(fmaxf(acc[j][mf][0] + b1s[c],     0.f)) |
                ((uint32_t)f16(fmaxf(acc[j][mf][1] + b1s[c + 1], 0.f)) << 16);
            const uint32_t h1 =
                (uint32_t)f16(fmaxf(acc[j][mf][2] + b1s[c],     0.f)) |
                ((uint32_t)f16(fmaxf(acc[j][mf][3] + b1s[c + 1], 0.f)) << 16);
            *(uint32_t*)(sm + OFF_H + r0 * P_A + c * 2) = h0;
            *(uint32_t*)(sm + OFF_H + r1 * P_A + c * 2) = h1;
        }
    }
    __syncthreads();

    // ================= phase 3: F = H @ Wn2 (img 2) =================
    gemm_phase(sb, OFF_H, 2, mw, nw, lane, acc);
    __syncthreads();   // all H (and X) reads done; Wf overlays them

    // ---- weighted feats: Wf[r][c] = (F + b2) * AE[r][c&7] ----
    #pragma unroll
    for (int mf = 0; mf < 2; ++mf) {
        const int r0 = mw * 32 + mf * 16 + g;
        const int r1 = r0 + 8;
        const float2 e0 = *(const float2*)(AE + r0 * 8 + tig * 2);
        const float2 e1 = *(const float2*)(AE + r1 * 8 + tig * 2);
        #pragma unroll
        for (int j = 0; j < 8; ++j) {
            const int c = nw * 64 + j * 8 + tig * 2;
            float2 s0, s1;
            s0.x = (acc[j][mf][0] + b2s[c])     * e0.x;
            s0.y = (acc[j][mf][1] + b2s[c + 1]) * e0.y;
            s1.x = (acc[j][mf][2] + b2s[c])     * e1.x;
            s1.y = (acc[j][mf][3] + b2s[c + 1]) * e1.y;
            *(float2*)(sm + OFF_WF + r0 * P_WF + c * 4) = s0;
            *(float2*)(sm + OFF_WF + r1 * P_WF + c * 4) = s1;
        }
    }
    __syncthreads();

    // ---- segmented reduction over 64 rows -> atomicAdd out (unnormalized) ----
    {
        const int c = t;
        float s = 0.f;
        int cur = -1;
        #pragma unroll 4
        for (int r = 0; r < 64; ++r) {
            const int gid = bbs[r];
            if (gid != cur) {
                if (cur >= 0) atomicAdd(out + (size_t)cur * 256 + c, s);
                cur = gid;
                s = 0.f;
            }
            if (gid >= 0) s += *(const float*)(sm + OFF_WF + r * P_WF + c * 4);
        }
        if (cur >= 0) atomicAdd(out + (size_t)cur * 256 + c, s);
    }
}

// ---------------------------------------------------------------------------
// k_norm: out[b][c] /= (ssum[b][c&7] + 1e-16)
// ---------------------------------------------------------------------------
__global__ __launch_bounds__(256)
void k_norm(float* __restrict__ out)
{
    const int b = blockIdx.x, c = threadIdx.x;
    out[(size_t)b * 256 + c] /= (g_ssum[b * 8 + (c & 7)] + 1e-16f);
}

// ---------------------------------------------------------------------------
extern "C" void kernel_launch(void* const* d_in, const int* in_sizes, int n_in,
                              void* d_out, int out_size)
{
    const float* x     = (const float*)d_in[0];
    const int*   batch = (const int*)d_in[1];
    const float* Wg1   = (const float*)d_in[2];
    const float* Wg2   = (const float*)d_in[3];
    const float* Wn1   = (const float*)d_in[4];
    const float* bn1   = (const float*)d_in[5];
    const float* Wn2   = (const float*)d_in[6];
    const float* bn2   = (const float*)d_in[7];
    float* out = (float*)d_out;

    const int n = in_sizes[0] / 256;
    const int B = out_size / 256;
    const int tiles64 = (n + 63) / 64;

    cudaFuncSetAttribute(k_main, cudaFuncAttributeMaxDynamicSharedMemorySize, SMEM_MAIN);

    k_prep<<<dim3(32, 3), 256>>>(Wn1, Wg1, Wn2, out, out_size);
    k_main<<<tiles64, 256, SMEM_MAIN>>>(x, Wg2, bn1, bn2, batch, out, n);
    k_norm<<<B, 256>>>(out);
}

// round 17
// speedup vs baseline: 2.2321x; 1.0414x over previous
#include <cuda_runtime.h>
#include <cuda_fp16.h>
#include <cstdint>
#include <cstddef>

// ---------------------------------------------------------------------------
//   x[N,256], batch[N] int32 sorted, W_g1[256,256], W_g2[256,8],
//   W_n1[256,256], b_n1[256], W_n2[256,256], b_n2[256] -> out[1024,256] fp32
//   Engine: mma.sync m16n8k16 FP16 1-pass, fp32 accum. Fully fused per
//   64-row tile; unnormalized exp(alpha) gating (max-sub cancels), k_norm
//   divides at the end. 256-thread CTAs, 2 CTAs/SM.
//   R17: barrier-minimized schedule (ph1+epi || ph2+Hwrite share no smem).
// ---------------------------------------------------------------------------

// fragment-ordered fp16 weights, 2 n-fragments packed per uint4:
// [w(3)][kstep(16)][nf2(16)][lane(32)] uint4  (img 0=Wn1, 1=Wg1, 2=Wn2)
__device__ uint4 g_Wfrag4[3 * 16 * 16 * 32];
__device__ float g_ssum[1024 * 8];   // per-graph per-head sum of exp(alpha)

// ---------------- helpers ---------------------------------------------------
__device__ __forceinline__ uint32_t smem_u32(const void* p) {
    uint32_t a;
    asm("{ .reg .u64 t; cvta.to.shared.u64 t, %1; cvt.u32.u64 %0, t; }"
        : "=r"(a) : "l"(p));
    return a;
}
__device__ __forceinline__ uint16_t f16(float v) {
    return __half_as_ushort(__float2half_rn(v));
}
__device__ __forceinline__ void ldsm4(uint32_t* a, uint32_t addr) {
    asm volatile("ldmatrix.sync.aligned.m8n8.x4.shared.b16 {%0,%1,%2,%3}, [%4];"
                 : "=r"(a[0]), "=r"(a[1]), "=r"(a[2]), "=r"(a[3]) : "r"(addr));
}
__device__ __forceinline__ void mma16816(float* c, const uint32_t* a,
                                         uint32_t b0, uint32_t b1) {
    asm volatile(
        "mma.sync.aligned.m16n8k16.row.col.f32.f16.f16.f32 "
        "{%0,%1,%2,%3},{%4,%5,%6,%7},{%8,%9},{%0,%1,%2,%3};"
        : "+f"(c[0]), "+f"(c[1]), "+f"(c[2]), "+f"(c[3])
        : "r"(a[0]), "r"(a[1]), "r"(a[2]), "r"(a[3]), "r"(b0), "r"(b1));
}

// ---------------- smem layout (bytes) ----------------------------------------
#define P_A 528                    // fp16 tile pitch (64 rows x 256 cols + pad)
#define OFF_X    0                 // 64*528 = 33792  (x fp16)
#define OFF_H    33792             // 33792           (H fp16)
#define P_WF 1032
#define OFF_WF   0                 // 66048, overlays X+H after GEMM3 reads
#define OFF_WG2  67584             // 8192
#define OFF_ALP  75776             // 2048 (64x8 fp32)
#define OFF_AE   77824             // 2048 (64x8 fp32 exp(alpha))
#define OFF_B1   79872             // 1024
#define OFF_B2   80896             // 1024
#define OFF_BB   81920             // 256 (64 ints)
#define SMEM_MAIN 82176

// ---------------------------------------------------------------------------
// k_prep: pack 3 weights into fragment-pair-ordered fp16 uint4;
// zero out[] and g_ssum (atomic targets).
// ---------------------------------------------------------------------------
__global__ void k_prep(const float* __restrict__ Wn1,
                       const float* __restrict__ Wg1,
                       const float* __restrict__ Wn2,
                       float* __restrict__ out, int out_elems)
{
    const float* W = (blockIdx.y == 0) ? Wn1 : (blockIdx.y == 1) ? Wg1 : Wn2;
    const int i = blockIdx.x * 256 + threadIdx.x;   // 0..8191
    const int lane = i & 31;
    const int nf2  = (i >> 5) & 15;
    const int ks   = i >> 9;
    const int k0   = ks * 16 + (lane & 3) * 2;

    uint4 o;
    {
        const int nn = (2 * nf2) * 8 + (lane >> 2);
        o.x = (uint32_t)f16(W[(k0 + 0) * 256 + nn]) |
              ((uint32_t)f16(W[(k0 + 1) * 256 + nn]) << 16);
        o.y = (uint32_t)f16(W[(k0 + 8) * 256 + nn]) |
              ((uint32_t)f16(W[(k0 + 9) * 256 + nn]) << 16);
    }
    {
        const int nn = (2 * nf2 + 1) * 8 + (lane >> 2);
        o.z = (uint32_t)f16(W[(k0 + 0) * 256 + nn]) |
              ((uint32_t)f16(W[(k0 + 1) * 256 + nn]) << 16);
        o.w = (uint32_t)f16(W[(k0 + 8) * 256 + nn]) |
              ((uint32_t)f16(W[(k0 + 9) * 256 + nn]) << 16);
    }
    g_Wfrag4[(((blockIdx.y * 16 + ks) * 16 + nf2) * 32) + lane] = o;

    const int gid = (blockIdx.y * gridDim.x + blockIdx.x) * 256 + threadIdx.x;
    const int tot = gridDim.x * gridDim.y * 256;
    for (int e = gid; e < out_elems; e += tot) out[e] = 0.f;
    for (int e = gid; e < 1024 * 8; e += tot) g_ssum[e] = 0.f;
}

// ---------------------------------------------------------------------------
// GEMM phase: D[64,256] = A(smem, pitch P_A, fp16) @ W_img^T.
// Warp tile 32x64: mw = w&1 (rows mw*32), nw = w>>1 (cols nw*64).
// ---------------------------------------------------------------------------
__device__ __forceinline__ void gemm_phase(uint32_t sb, int offA, int img,
                                           int mw, int nw, int lane,
                                           float (&acc)[8][2][4])
{
    #pragma unroll
    for (int j = 0; j < 8; ++j)
        #pragma unroll
        for (int mf = 0; mf < 2; ++mf)
            #pragma unroll
            for (int q = 0; q < 4; ++q) acc[j][mf][q] = 0.f;

    #pragma unroll
    for (int ks = 0; ks < 16; ++ks) {
        const uint32_t abase = sb + offA + (mw * 32 + (lane & 15)) * P_A
                               + ks * 32 + ((lane >> 4) << 4);
        uint32_t ah0[4], ah1[4];
        ldsm4(ah0, abase);
        ldsm4(ah1, abase + 16 * P_A);
        const int fb = ((img * 16 + ks) * 16 + nw * 4) * 32 + lane;
        #pragma unroll
        for (int q = 0; q < 4; ++q) {
            const uint4 b = __ldg(&g_Wfrag4[fb + q * 32]);
            const int j0 = 2 * q, j1 = 2 * q + 1;
            mma16816(acc[j0][0], ah0, b.x, b.y);
            mma16816(acc[j0][1], ah1, b.x, b.y);
            mma16816(acc[j1][0], ah0, b.z, b.w);
            mma16816(acc[j1][1], ah1, b.z, b.w);
        }
    }
}

// ---------------------------------------------------------------------------
// k_main: fully fused per 64-row tile, 4 barriers total.
// ---------------------------------------------------------------------------
__global__ __launch_bounds__(256, 2)
void k_main(const float* __restrict__ x,
            const float* __restrict__ Wg2,
            const float* __restrict__ bn1,
            const float* __restrict__ bn2,
            const int* __restrict__ batch,
            float* __restrict__ out,
            int n)
{
    extern __shared__ unsigned char sm[];
    const uint32_t sb = smem_u32(sm);
    float* Wg2s     = (float*)(sm + OFF_WG2);
    float* alpha_sm = (float*)(sm + OFF_ALP);
    float* AE       = (float*)(sm + OFF_AE);
    float* b1s      = (float*)(sm + OFF_B1);
    float* b2s      = (float*)(sm + OFF_B2);
    int*   bbs      = (int*)(sm + OFF_BB);

    const int t = threadIdx.x;
    const int lane = t & 31, w = t >> 5;
    const int g = lane >> 2, tig = lane & 3;
    const int m0 = blockIdx.x * 64;
    const int mw = w & 1, nw = w >> 1;

    #pragma unroll
    for (int q = 0; q < 8; ++q) Wg2s[t + q * 256] = Wg2[t + q * 256];
    b1s[t] = bn1[t];
    b2s[t] = bn2[t];
    if (t < 64) bbs[t] = (m0 + t < n) ? batch[m0 + t] : -1;
    alpha_sm[t] = 0.f;
    alpha_sm[t + 256] = 0.f;

    // ---- stage x[m0:m0+64, 0:256] -> fp16 smem ----
    #pragma unroll
    for (int e = 0; e < 16; ++e) {
        const int idx = t + e * 256;            // 0..4095 float4s
        const int row = idx >> 6, q = idx & 63;
        const int m = m0 + row;
        float4 v = make_float4(0.f, 0.f, 0.f, 0.f);
        if (m < n) v = ((const float4*)(x + (size_t)m * 256))[q];
        uint2 hp;
        hp.x = (uint32_t)f16(v.x) | ((uint32_t)f16(v.y) << 16);
        hp.y = (uint32_t)f16(v.z) | ((uint32_t)f16(v.w) << 16);
        *(uint2*)(sm + OFF_X + row * P_A + q * 8) = hp;
    }
    __syncthreads();   // B0

    float acc[8][2][4];

    // ================= phase 1: Dg = x @ Wg1 (img 1) =================
    gemm_phase(sb, OFF_X, 1, mw, nw, lane, acc);

    // ---- alpha partial = relu(Dg) @ Wg2 -> smem atomics (no barrier after) ----
    {
        float pa[4][8];
        #pragma unroll
        for (int s = 0; s < 4; ++s)
            #pragma unroll
            for (int h = 0; h < 8; ++h) pa[s][h] = 0.f;

        #pragma unroll
        for (int mf = 0; mf < 2; ++mf)
            #pragma unroll
            for (int j = 0; j < 8; ++j) {
                const int c = nw * 64 + j * 8 + tig * 2;
                const float d0 = fmaxf(acc[j][mf][0], 0.f);
                const float d1 = fmaxf(acc[j][mf][1], 0.f);
                const float d2 = fmaxf(acc[j][mf][2], 0.f);
                const float d3 = fmaxf(acc[j][mf][3], 0.f);
                const float4* wa = (const float4*)(Wg2s + c * 8);
                const float4* wb = (const float4*)(Wg2s + (c + 1) * 8);
                const float4 a0 = wa[0], a1 = wa[1], b0 = wb[0], b1 = wb[1];
                float* p0 = pa[mf * 2];
                float* p1 = pa[mf * 2 + 1];
                p0[0] = fmaf(d0, a0.x, fmaf(d1, b0.x, p0[0]));
                p0[1] = fmaf(d0, a0.y, fmaf(d1, b0.y, p0[1]));
                p0[2] = fmaf(d0, a0.z, fmaf(d1, b0.z, p0[2]));
                p0[3] = fmaf(d0, a0.w, fmaf(d1, b0.w, p0[3]));
                p0[4] = fmaf(d0, a1.x, fmaf(d1, b1.x, p0[4]));
                p0[5] = fmaf(d0, a1.y, fmaf(d1, b1.y, p0[5]));
                p0[6] = fmaf(d0, a1.z, fmaf(d1, b1.z, p0[6]));
                p0[7] = fmaf(d0, a1.w, fmaf(d1, b1.w, p0[7]));
                p1[0] = fmaf(d2, a0.x, fmaf(d3, b0.x, p1[0]));
                p1[1] = fmaf(d2, a0.y, fmaf(d3, b0.y, p1[1]));
                p1[2] = fmaf(d2, a0.z, fmaf(d3, b0.z, p1[2]));
                p1[3] = fmaf(d2, a0.w, fmaf(d3, b0.w, p1[3]));
                p1[4] = fmaf(d2, a1.x, fmaf(d3, b1.x, p1[4]));
                p1[5] = fmaf(d2, a1.y, fmaf(d3, b1.y, p1[5]));
                p1[6] = fmaf(d2, a1.z, fmaf(d3, b1.z, p1[6]));
                p1[7] = fmaf(d2, a1.w, fmaf(d3, b1.w, p1[7]));
            }
        #pragma unroll
        for (int off = 1; off <= 2; off <<= 1)
            #pragma unroll
            for (int s = 0; s < 4; ++s)
                #pragma unroll
                for (int h = 0; h < 8; ++h)
                    pa[s][h] += __shfl_xor_sync(0xffffffffu, pa[s][h], off);
        if (tig == 0) {
            #pragma unroll
            for (int s = 0; s < 4; ++s) {
                const int row = mw * 32 + (s >> 1) * 16 + (s & 1) * 8 + g;
                #pragma unroll
                for (int h = 0; h < 8; ++h)
                    atomicAdd(&alpha_sm[row * 8 + h], pa[s][h]);
            }
        }
    }

    // ================= phase 2: Dn = x @ Wn1 (img 0), no barrier before ======
    gemm_phase(sb, OFF_X, 0, mw, nw, lane, acc);

    // ---- H = relu(Dn + b1) -> fp16 smem (disjoint from X/alpha regions) ----
    #pragma unroll
    for (int mf = 0; mf < 2; ++mf) {
        const int r0 = mw * 32 + mf * 16 + g;
        const int r1 = r0 + 8;
        #pragma unroll
        for (int j = 0; j < 8; ++j) {
            const int c = nw * 64 + j * 8 + tig * 2;
            const uint32_t h0 =
                (uint32_t)f16(fmaxf(acc[j][mf][0] + b1s[c],     0.f)) |
                ((uint32_t)f16(fmaxf(acc[j][mf][1] + b1s[c + 1], 0.f)) << 16);
            const uint32_t h1 =
                (uint32_t)f16(fmaxf(acc[j][mf][2] + b1s[c],     0.f)) |
                ((uint32_t)f16(fmaxf(acc[j][mf][3] + b1s[c + 1], 0.f)) << 16);
            *(uint32_t*)(sm + OFF_H + r0 * P_A + c * 2) = h0;
            *(uint32_t*)(sm + OFF_H + r1 * P_A + c * 2) = h1;
        }
    }
    __syncthreads();   // B1: alpha_sm final, H complete

    // ---- AE = exp(alpha) (unnormalized softmax numerator) ----
    AE[t]       = __expf(alpha_sm[t]);
    AE[t + 256] = __expf(alpha_sm[t + 256]);

    // ================= phase 3: F = H @ Wn2 (img 2) =================
    gemm_phase(sb, OFF_H, 2, mw, nw, lane, acc);
    __syncthreads();   // B2: X/H reads done (Wf overlays), AE visible

    // ---- ssum: segmented per-graph/head sum of AE -> global atomics ----
    if (t < 16) {
        const int h = t & 7, half = t >> 3;
        float s = 0.f;
        int cur = -1;
        for (int r = half * 32; r < half * 32 + 32; ++r) {
            const int gid = bbs[r];
            if (gid != cur) {
                if (cur >= 0) atomicAdd(&g_ssum[cur * 8 + h], s);
                cur = gid;
                s = 0.f;
            }
            if (gid >= 0) s += AE[r * 8 + h];
        }
        if (cur >= 0) atomicAdd(&g_ssum[cur * 8 + h], s);
    }

    // ---- weighted feats: Wf[r][c] = (F + b2) * AE[r][c&7] ----
    #pragma unroll
    for (int mf = 0; mf < 2; ++mf) {
        const int r0 = mw * 32 + mf * 16 + g;
        const int r1 = r0 + 8;
        const float2 e0 = *(const float2*)(AE + r0 * 8 + tig * 2);
        const float2 e1 = *(const float2*)(AE + r1 * 8 + tig * 2);
        #pragma unroll
        for (int j = 0; j < 8; ++j) {
            const int c = nw * 64 + j * 8 + tig * 2;
            float2 s0, s1;
            s0.x = (acc[j][mf][0] + b2s[c])     * e0.x;
            s0.y = (acc[j][mf][1] + b2s[c + 1]) * e0.y;
            s1.x = (acc[j][mf][2] + b2s[c])     * e1.x;
            s1.y = (acc[j][mf][3] + b2s[c + 1]) * e1.y;
            *(float2*)(sm + OFF_WF + r0 * P_WF + c * 4) = s0;
            *(float2*)(sm + OFF_WF + r1 * P_WF + c * 4) = s1;
        }
    }
    __syncthreads();   // B3

    // ---- segmented reduction over 64 rows -> atomicAdd out (unnormalized) ----
    {
        const int c = t;
        float s = 0.f;
        int cur = -1;
        #pragma unroll 4
        for (int r = 0; r < 64; ++r) {
            const int gid = bbs[r];
            if (gid != cur) {
                if (cur >= 0) atomicAdd(out + (size_t)cur * 256 + c, s);
                cur = gid;
                s = 0.f;
            }
            if (gid >= 0) s += *(const float*)(sm + OFF_WF + r * P_WF + c * 4);
        }
        if (cur >= 0) atomicAdd(out + (size_t)cur * 256 + c, s);
    }
}

// ---------------------------------------------------------------------------
// k_norm: out[b][c] /= (ssum[b][c&7] + 1e-16)
// ---------------------------------------------------------------------------
__global__ __launch_bounds__(256)
void k_norm(float* __restrict__ out)
{
    const int b = blockIdx.x, c = threadIdx.x;
    out[(size_t)b * 256 + c] /= (g_ssum[b * 8 + (c & 7)] + 1e-16f);
}

// ---------------------------------------------------------------------------
extern "C" void kernel_launch(void* const* d_in, const int* in_sizes, int n_in,
                              void* d_out, int out_size)
{
    const float* x     = (const float*)d_in[0];
    const int*   batch = (const int*)d_in[1];
    const float* Wg1   = (const float*)d_in[2];
    const float* Wg2   = (const float*)d_in[3];
    const float* Wn1   = (const float*)d_in[4];
    const float* bn1   = (const float*)d_in[5];
    const float* Wn2   = (const float*)d_in[6];
    const float* bn2   = (const float*)d_in[7];
    float* out = (float*)d_out;

    const int n = in_sizes[0] / 256;
    const int B = out_size / 256;
    const int tiles64 = (n + 63) / 64;

    cudaFuncSetAttribute(k_main, cudaFuncAttributeMaxDynamicSharedMemorySize, SMEM_MAIN);

    k_prep<<<dim3(32, 3), 256>>>(Wn1, Wg1, Wn2, out, out_size);
    k_main<<<tiles64, 256, SMEM_MAIN>>>(x, Wg2, bn1, bn2, batch, out, n);
    k_norm<<<B, 256>>>(out);
}